// round 1
// baseline (speedup 1.0000x reference)
#include <cuda_runtime.h>
#include <math.h>

#define EPSF 1e-6f

// Problem constants: B=4, S=1024, D=1024, H=16, DH=64, F=4096, M=B*S=4096
// Scratch (static device globals; allocation-free per harness rules)
__device__ float g_xn [4096 * 1024];       // 16 MB  LN output (reused for LN2)
__device__ float g_q  [4096 * 1024];       // 16 MB  q  (reused for attn_out)
__device__ float g_k  [4096 * 1024];       // 16 MB
__device__ float g_v  [4096 * 1024];       // 16 MB
__device__ float g_res[4096 * 1024];       // 16 MB  residual after attention block
__device__ float g_big[64 * 1024 * 1024];  // 256 MB scores [B,H,S,S]; later g1/g2 of FFN

// ---------------------------------------------------------------------------
// LayerNorm over D=1024. One block (256 threads) per row, float4 per thread.
// ---------------------------------------------------------------------------
__global__ __launch_bounds__(256) void ln_kernel(
    const float* __restrict__ in, const float* __restrict__ sc,
    const float* __restrict__ bi, float* __restrict__ out)
{
    const int row = blockIdx.x;
    const int t = threadIdx.x;
    const float4* x4 = (const float4*)(in + (size_t)row * 1024);
    float4 v = x4[t];
    float s  = v.x + v.y + v.z + v.w;
    float ss = v.x * v.x + v.y * v.y + v.z * v.z + v.w * v.w;
    #pragma unroll
    for (int o = 16; o; o >>= 1) {
        s  += __shfl_xor_sync(0xffffffffu, s,  o);
        ss += __shfl_xor_sync(0xffffffffu, ss, o);
    }
    __shared__ float sred[8], ssred[8];
    if ((t & 31) == 0) { sred[t >> 5] = s; ssred[t >> 5] = ss; }
    __syncthreads();
    float tot = 0.f, tots = 0.f;
    #pragma unroll
    for (int w = 0; w < 8; w++) { tot += sred[w]; tots += ssred[w]; }
    const float mean = tot * (1.f / 1024.f);
    const float var  = tots * (1.f / 1024.f) - mean * mean;
    const float inv  = rsqrtf(var + EPSF);
    float4 sv = ((const float4*)sc)[t];
    float4 bv = ((const float4*)bi)[t];
    float4 o4;
    o4.x = (v.x - mean) * inv * sv.x + bv.x;
    o4.y = (v.y - mean) * inv * sv.y + bv.y;
    o4.z = (v.z - mean) * inv * sv.z + bv.z;
    o4.w = (v.w - mean) * inv * sv.w + bv.w;
    ((float4*)(out + (size_t)row * 1024))[t] = o4;
}

// ---------------------------------------------------------------------------
// QK-norm: LayerNorm over DH=64 with (H,DH) scale/bias. One warp per (b,s,h).
// In-place.
// ---------------------------------------------------------------------------
__global__ __launch_bounds__(256) void qknorm_kernel(
    float* __restrict__ q, const float* __restrict__ sc, const float* __restrict__ bi)
{
    const int gw   = (blockIdx.x * 256 + threadIdx.x) >> 5;  // 0 .. 65535
    const int lane = threadIdx.x & 31;
    const int h  = gw & 15;
    const int bs = gw >> 4;
    float* p = q + (size_t)bs * 1024 + h * 64;
    float2 v = *(float2*)(p + lane * 2);
    float s  = v.x + v.y;
    float ss = v.x * v.x + v.y * v.y;
    #pragma unroll
    for (int o = 16; o; o >>= 1) {
        s  += __shfl_xor_sync(0xffffffffu, s,  o);
        ss += __shfl_xor_sync(0xffffffffu, ss, o);
    }
    const float mean = s * (1.f / 64.f);
    const float var  = ss * (1.f / 64.f) - mean * mean;
    const float inv  = rsqrtf(var + EPSF);
    const float* scp = sc + h * 64;
    const float* bip = bi + h * 64;
    v.x = (v.x - mean) * inv * scp[lane * 2 + 0] + bip[lane * 2 + 0];
    v.y = (v.y - mean) * inv * scp[lane * 2 + 1] + bip[lane * 2 + 1];
    *(float2*)(p + lane * 2) = v;
}

// ---------------------------------------------------------------------------
// Generic SGEMM: C[M,N] = A[M,K] @ B[K,N] + bias[N] (+ Res[M,N]).
// 128x128 tile, BK=8, 256 threads, 8x8 micro-tile per thread.
// All dims are multiples of the tile sizes for this problem.
// ---------------------------------------------------------------------------
template <bool HAS_RES>
__global__ __launch_bounds__(256) void gemm128(
    const float* __restrict__ A, const float* __restrict__ B,
    const float* __restrict__ bias, const float* __restrict__ Res,
    float* __restrict__ C, int N, int K)
{
    __shared__ float As[8][128];
    __shared__ float Bs[8][128];
    const int t  = threadIdx.x;
    const int tx = t & 15, ty = t >> 4;
    const int bm = blockIdx.y * 128;
    const int bn = blockIdx.x * 128;
    const float* Ab = A + (size_t)bm * K;
    const float* Bb = B + bn;

    float acc[8][8];
    #pragma unroll
    for (int i = 0; i < 8; i++)
        #pragma unroll
        for (int j = 0; j < 8; j++) acc[i][j] = 0.f;

    const int arow = t >> 1;          // 0..127
    const int acol = (t & 1) << 2;    // 0 or 4
    const int brow = t >> 5;          // 0..7
    const int bcol = (t & 31) << 2;   // 0..124

    for (int k0 = 0; k0 < K; k0 += 8) {
        float4 av = *(const float4*)(Ab + (size_t)arow * K + k0 + acol);
        As[acol + 0][arow] = av.x;
        As[acol + 1][arow] = av.y;
        As[acol + 2][arow] = av.z;
        As[acol + 3][arow] = av.w;
        *(float4*)(&Bs[brow][bcol]) = *(const float4*)(Bb + (size_t)(k0 + brow) * N + bcol);
        __syncthreads();
        #pragma unroll
        for (int kk = 0; kk < 8; ++kk) {
            float af[8], bf[8];
            #pragma unroll
            for (int i = 0; i < 4; i++) {
                af[i]     = As[kk][(ty << 2) + i];
                af[i + 4] = As[kk][64 + (ty << 2) + i];
                bf[i]     = Bs[kk][(tx << 2) + i];
                bf[i + 4] = Bs[kk][64 + (tx << 2) + i];
            }
            #pragma unroll
            for (int i = 0; i < 8; i++)
                #pragma unroll
                for (int j = 0; j < 8; j++)
                    acc[i][j] += af[i] * bf[j];
        }
        __syncthreads();
    }

    #pragma unroll
    for (int i = 0; i < 8; i++) {
        const int r = bm + ((i < 4) ? (ty << 2) + i : 64 + (ty << 2) + (i - 4));
        #pragma unroll
        for (int j = 0; j < 8; j++) {
            const int c = bn + ((j < 4) ? (tx << 2) + j : 64 + (tx << 2) + (j - 4));
            float val = acc[i][j] + bias[c];
            if (HAS_RES) val += Res[(size_t)r * N + c];
            C[(size_t)r * N + c] = val;
        }
    }
}

// ---------------------------------------------------------------------------
// Scores: S[b,h,q,t] = (q . k) / sqrt(64).  NT batched GEMM, 64x64 tile, K=64.
// q,k layout [B,S,H*DH] (row stride 1024, head offset h*64).
// Transposed smem layout (d-major) keeps compute-load conflicts at 2-way.
// ---------------------------------------------------------------------------
__global__ __launch_bounds__(256) void score_gemm(
    const float* __restrict__ q, const float* __restrict__ k, float* __restrict__ out)
{
    __shared__ float Qs[64][65];   // [d][q_row]
    __shared__ float Ks[64][65];   // [d][k_row]
    const int bh = blockIdx.z;
    const int b = bh >> 4, h = bh & 15;
    const float* qb = q + ((size_t)b * 1024 + blockIdx.x * 64) * 1024 + h * 64;
    const float* kb = k + ((size_t)b * 1024 + blockIdx.y * 64) * 1024 + h * 64;
    const int t = threadIdx.x;
    #pragma unroll
    for (int i = 0; i < 4; i++) {
        const int idx = t + 256 * i;
        const int row = idx >> 4;
        const int c4  = (idx & 15) << 2;
        float4 qv = *(const float4*)(qb + (size_t)row * 1024 + c4);
        float4 kv = *(const float4*)(kb + (size_t)row * 1024 + c4);
        Qs[c4 + 0][row] = qv.x; Qs[c4 + 1][row] = qv.y;
        Qs[c4 + 2][row] = qv.z; Qs[c4 + 3][row] = qv.w;
        Ks[c4 + 0][row] = kv.x; Ks[c4 + 1][row] = kv.y;
        Ks[c4 + 2][row] = kv.z; Ks[c4 + 3][row] = kv.w;
    }
    __syncthreads();
    const int tx = t & 15, ty = t >> 4;
    float acc[4][4] = {};
    #pragma unroll 8
    for (int d = 0; d < 64; ++d) {
        float qf[4], kf[4];
        #pragma unroll
        for (int i = 0; i < 4; i++) {
            qf[i] = Qs[d][(ty << 2) + i];
            kf[i] = Ks[d][(tx << 2) + i];
        }
        #pragma unroll
        for (int i = 0; i < 4; i++)
            #pragma unroll
            for (int j = 0; j < 4; j++)
                acc[i][j] += qf[i] * kf[j];
    }
    float* ob = out + ((size_t)bh << 20) + (size_t)(blockIdx.x * 64) * 1024 + blockIdx.y * 64;
    #pragma unroll
    for (int i = 0; i < 4; i++)
        #pragma unroll
        for (int j = 0; j < 4; j++)
            ob[(size_t)((ty << 2) + i) * 1024 + (tx << 2) + j] = acc[i][j] * 0.125f;
}

// ---------------------------------------------------------------------------
// Row softmax over 1024 (in-place). One block per row of g_big.
// ---------------------------------------------------------------------------
__global__ __launch_bounds__(256) void softmax_kernel(float* __restrict__ s)
{
    const size_t row = blockIdx.x;
    float4* p = (float4*)(s + row * 1024);
    const int t = threadIdx.x;
    float4 v = p[t];
    float m = fmaxf(fmaxf(v.x, v.y), fmaxf(v.z, v.w));
    #pragma unroll
    for (int o = 16; o; o >>= 1) m = fmaxf(m, __shfl_xor_sync(0xffffffffu, m, o));
    __shared__ float redm[8], reds[8];
    if ((t & 31) == 0) redm[t >> 5] = m;
    __syncthreads();
    float mm = redm[0];
    #pragma unroll
    for (int w = 1; w < 8; w++) mm = fmaxf(mm, redm[w]);
    v.x = __expf(v.x - mm); v.y = __expf(v.y - mm);
    v.z = __expf(v.z - mm); v.w = __expf(v.w - mm);
    float sum = v.x + v.y + v.z + v.w;
    #pragma unroll
    for (int o = 16; o; o >>= 1) sum += __shfl_xor_sync(0xffffffffu, sum, o);
    if ((t & 31) == 0) reds[t >> 5] = sum;
    __syncthreads();
    float tot = 0.f;
    #pragma unroll
    for (int w = 0; w < 8; w++) tot += reds[w];
    const float inv = 1.f / tot;
    v.x *= inv; v.y *= inv; v.z *= inv; v.w *= inv;
    p[t] = v;
}

// ---------------------------------------------------------------------------
// attn @ V: out[b,q,h*64+d] = sum_t attn[b,h,q,t] * v[b,t,h*64+d].
// NN batched GEMM, 64(M) x 64(N) tile, BK=32, K=1024.
// ---------------------------------------------------------------------------
__global__ __launch_bounds__(256) void av_gemm(
    const float* __restrict__ attn, const float* __restrict__ v, float* __restrict__ out)
{
    __shared__ float As[64][33];
    __shared__ float Bs[32][65];
    const int bh = blockIdx.y;
    const int b = bh >> 4, h = bh & 15;
    const float* ab = attn + ((size_t)bh << 20) + (size_t)blockIdx.x * 64 * 1024;
    const float* vb = v + (size_t)b * 1024 * 1024 + h * 64;
    const int t = threadIdx.x;
    const int tx = t & 15, ty = t >> 4;
    float acc[4][4] = {};
    for (int k0 = 0; k0 < 1024; k0 += 32) {
        #pragma unroll
        for (int i = 0; i < 2; i++) {
            const int idx = t + 256 * i;           // 0..511
            const int ar  = idx >> 3;              // 0..63
            const int ac4 = (idx & 7) << 2;        // 0..28
            float4 a4 = *(const float4*)(ab + (size_t)ar * 1024 + k0 + ac4);
            As[ar][ac4 + 0] = a4.x; As[ar][ac4 + 1] = a4.y;
            As[ar][ac4 + 2] = a4.z; As[ar][ac4 + 3] = a4.w;
            const int br  = idx >> 4;              // 0..31
            const int bc4 = (idx & 15) << 2;       // 0..60
            float4 b4 = *(const float4*)(vb + (size_t)(k0 + br) * 1024 + bc4);
            Bs[br][bc4 + 0] = b4.x; Bs[br][bc4 + 1] = b4.y;
            Bs[br][bc4 + 2] = b4.z; Bs[br][bc4 + 3] = b4.w;
        }
        __syncthreads();
        #pragma unroll 8
        for (int kk = 0; kk < 32; ++kk) {
            float a[4], bb[4];
            #pragma unroll
            for (int i = 0; i < 4; i++) {
                a[i]  = As[(ty << 2) + i][kk];
                bb[i] = Bs[kk][(tx << 2) + i];
            }
            #pragma unroll
            for (int i = 0; i < 4; i++)
                #pragma unroll
                for (int j = 0; j < 4; j++)
                    acc[i][j] += a[i] * bb[j];
        }
        __syncthreads();
    }
    float* ob = out + (size_t)b * 1024 * 1024 + (size_t)blockIdx.x * 64 * 1024 + h * 64;
    #pragma unroll
    for (int i = 0; i < 4; i++)
        #pragma unroll
        for (int j = 0; j < 4; j++)
            ob[(size_t)((ty << 2) + i) * 1024 + (tx << 2) + j] = acc[i][j];
}

// ---------------------------------------------------------------------------
// GeGLU: g1 <- g1 * gelu_tanh(g2), elementwise over 16M values (float4).
// ---------------------------------------------------------------------------
__device__ __forceinline__ float gelu_t(float x)
{
    return 0.5f * x * (1.f + tanhf(0.7978845608028654f * (x + 0.044715f * x * x * x)));
}

__global__ __launch_bounds__(256) void geglu_kernel(
    float* __restrict__ g1, const float* __restrict__ g2)
{
    const size_t i = (size_t)blockIdx.x * 256 + threadIdx.x;
    float4 a = ((const float4*)g1)[i];
    float4 c = ((const float4*)g2)[i];
    a.x *= gelu_t(c.x);
    a.y *= gelu_t(c.y);
    a.z *= gelu_t(c.z);
    a.w *= gelu_t(c.w);
    ((float4*)g1)[i] = a;
}

// ---------------------------------------------------------------------------
// Launch
// ---------------------------------------------------------------------------
extern "C" void kernel_launch(void* const* d_in, const int* in_sizes, int n_in,
                              void* d_out, int out_size)
{
    (void)in_sizes; (void)n_in; (void)out_size;
    const float* x     = (const float*)d_in[0];
    // d_in[1] = z (unused by the module)
    const float* ln1_s = (const float*)d_in[2];
    const float* ln1_b = (const float*)d_in[3];
    const float* Wq    = (const float*)d_in[4];
    const float* bq    = (const float*)d_in[5];
    const float* Wk    = (const float*)d_in[6];
    const float* bk    = (const float*)d_in[7];
    const float* Wv    = (const float*)d_in[8];
    const float* bv    = (const float*)d_in[9];
    const float* qn_s  = (const float*)d_in[10];
    const float* qn_b  = (const float*)d_in[11];
    const float* kn_s  = (const float*)d_in[12];
    const float* kn_b  = (const float*)d_in[13];
    const float* Wo    = (const float*)d_in[14];
    const float* bo    = (const float*)d_in[15];
    const float* ln2_s = (const float*)d_in[16];
    const float* ln2_b = (const float*)d_in[17];
    const float* W1    = (const float*)d_in[18];
    const float* b1    = (const float*)d_in[19];
    const float* W2    = (const float*)d_in[20];
    const float* b2    = (const float*)d_in[21];
    const float* W3    = (const float*)d_in[22];
    const float* b3    = (const float*)d_in[23];

    float *xn, *q, *k, *v, *res, *big;
    cudaGetSymbolAddress((void**)&xn,  g_xn);
    cudaGetSymbolAddress((void**)&q,   g_q);
    cudaGetSymbolAddress((void**)&k,   g_k);
    cudaGetSymbolAddress((void**)&v,   g_v);
    cudaGetSymbolAddress((void**)&res, g_res);
    cudaGetSymbolAddress((void**)&big, g_big);

    float* out = (float*)d_out;

    // 1. LN1
    ln_kernel<<<4096, 256>>>(x, ln1_s, ln1_b, xn);

    // 2-4. QKV projections  (M=4096, N=1024, K=1024)
    dim3 gqkv(1024 / 128, 4096 / 128);
    gemm128<false><<<gqkv, 256>>>(xn, Wq, bq, nullptr, q, 1024, 1024);
    gemm128<false><<<gqkv, 256>>>(xn, Wk, bk, nullptr, k, 1024, 1024);
    gemm128<false><<<gqkv, 256>>>(xn, Wv, bv, nullptr, v, 1024, 1024);

    // 5-6. QK-norm
    qknorm_kernel<<<8192, 256>>>(q, qn_s, qn_b);
    qknorm_kernel<<<8192, 256>>>(k, kn_s, kn_b);

    // 7. scores = q k^T / sqrt(DH)
    score_gemm<<<dim3(16, 16, 64), 256>>>(q, k, big);

    // 8. softmax over keys
    softmax_kernel<<<65536, 256>>>(big);

    // 9. attn @ V -> attn_out (reuse q)
    av_gemm<<<dim3(16, 64), 256>>>(big, v, q);

    // 10. O projection + residual with input x
    gemm128<true><<<gqkv, 256>>>(q, Wo, bo, x, res, 1024, 1024);

    // 11. LN2 (reuse xn)
    ln_kernel<<<4096, 256>>>(res, ln2_s, ln2_b, xn);

    // 12-13. FFN up projections (M=4096, N=4096, K=1024) -> g1, g2 in g_big
    dim3 gffn(4096 / 128, 4096 / 128);
    float* h1 = big;
    float* h2 = big + (size_t)16777216;
    gemm128<false><<<gffn, 256>>>(xn, W1, b1, nullptr, h1, 4096, 1024);
    gemm128<false><<<gffn, 256>>>(xn, W2, b2, nullptr, h2, 4096, 1024);

    // 14. GeGLU: h1 <- h1 * gelu(h2)
    geglu_kernel<<<16384, 256>>>(h1, h2);

    // 15. Down projection + residual -> d_out  (M=4096, N=1024, K=4096)
    dim3 gout(1024 / 128, 4096 / 128);
    gemm128<true><<<gout, 256>>>(h1, W3, b3, res, out, 1024, 4096);
}

// round 2
// speedup vs baseline: 2.1361x; 2.1361x over previous
#include <cuda_runtime.h>
#include <math.h>
#include <stdint.h>

#define EPSF 1e-6f

// Problem constants: B=4, S=1024, D=1024, H=16, DH=64, F=4096, M=B*S=4096
// Scratch (static device globals; allocation-free per harness rules)
__device__ float g_xn [4096 * 1024];       // 16 MB  LN output (reused for LN2)
__device__ float g_q  [4096 * 1024];       // 16 MB  q  (reused for attn_out)
__device__ float g_k  [4096 * 1024];       // 16 MB
__device__ float g_v  [4096 * 1024];       // 16 MB
__device__ float g_res[4096 * 1024];       // 16 MB  residual after attention block
__device__ float g_big[64 * 1024 * 1024];  // 256 MB scores [B,H,S,S]; later g1/g2 of FFN

// ---------------------------------------------------------------------------
// Helpers: cp.async + tf32
// ---------------------------------------------------------------------------
__device__ __forceinline__ void cp_async16(uint32_t dst_smem, const void* src)
{
    asm volatile("cp.async.cg.shared.global [%0], [%1], 16;\n" :: "r"(dst_smem), "l"(src));
}
__device__ __forceinline__ void cp_commit() { asm volatile("cp.async.commit_group;\n"); }
__device__ __forceinline__ void cp_wait0()  { asm volatile("cp.async.wait_group 0;\n"); }

__device__ __forceinline__ uint32_t f2tf32(float x)
{
    uint32_t r;
    asm("cvt.rna.tf32.f32 %0, %1;\n" : "=r"(r) : "f"(x));
    return r;
}
__device__ __forceinline__ uint32_t smem_u32(const void* p)
{
    uint32_t a;
    asm("{ .reg .u64 t; cvta.to.shared.u64 t, %1; cvt.u32.u64 %0, t; }" : "=r"(a) : "l"(p));
    return a;
}
__device__ __forceinline__ void mma_tf32(float c[4], const uint32_t a[4], const uint32_t b[2])
{
    asm volatile(
        "mma.sync.aligned.m16n8k8.row.col.f32.tf32.tf32.f32 "
        "{%0,%1,%2,%3}, {%4,%5,%6,%7}, {%8,%9}, {%0,%1,%2,%3};\n"
        : "+f"(c[0]), "+f"(c[1]), "+f"(c[2]), "+f"(c[3])
        : "r"(a[0]), "r"(a[1]), "r"(a[2]), "r"(a[3]), "r"(b[0]), "r"(b[1]));
}

// ---------------------------------------------------------------------------
// TF32 tensor-core GEMM: C[M,N] = A[M,K] @ B[K,N] + bias[N] (+ Res).
// BM=128 BN=128 BK=16, 256 threads (8 warps, 64x32 warp tiles), cp.async
// double buffering. Smem strides 20 / 136 floats -> conflict-free LDS.
// ---------------------------------------------------------------------------
template <bool HAS_RES>
__global__ __launch_bounds__(256) void gemm_tf32(
    const float* __restrict__ A, const float* __restrict__ B,
    const float* __restrict__ bias, const float* __restrict__ Res,
    float* __restrict__ C, int N, int K)
{
    __shared__ float As[2][128 * 20];   // 20480 B
    __shared__ float Bs[2][16 * 136];   // 17408 B

    const int t    = threadIdx.x;
    const int lane = t & 31;
    const int warp = t >> 5;
    const int wm   = (warp >> 2) * 64;  // warp row offset in tile
    const int wn   = (warp & 3) * 32;   // warp col offset in tile
    const int bm   = blockIdx.y * 128;
    const int bn   = blockIdx.x * 128;

    // cp.async load maps
    const int a_row = t >> 1;                 // 0..127
    const int a_c4  = (t & 1) << 3;           // 0 or 8 -> two float4 chunks each
    const int b_row = t >> 5;                 // 0..7  (two passes -> 0..15)
    const int b_c4  = (lane) << 2;            // 0..124

    const float* Ag = A + (size_t)(bm + a_row) * K + a_c4;
    const float* Bg = B + bn + b_c4;

    float acc[4][4][4];
    #pragma unroll
    for (int mt = 0; mt < 4; mt++)
        #pragma unroll
        for (int nt = 0; nt < 4; nt++)
            #pragma unroll
            for (int i = 0; i < 4; i++) acc[mt][nt][i] = 0.f;

    uint32_t sA0 = smem_u32(&As[0][0]);
    uint32_t sB0 = smem_u32(&Bs[0][0]);

    auto load_stage = [&](int buf, int k0) {
        uint32_t da = sA0 + (buf * 128 * 20 + a_row * 20 + a_c4) * 4;
        cp_async16(da,      Ag + k0);
        cp_async16(da + 16, Ag + k0 + 4);
        uint32_t db = sB0 + (buf * 16 * 136 + b_row * 136 + b_c4) * 4;
        cp_async16(db, Bg + (size_t)(k0 + b_row) * N);
        cp_async16(db + 8 * 136 * 4, Bg + (size_t)(k0 + b_row + 8) * N);
    };

    load_stage(0, 0);
    cp_commit();

    const int nIter = K >> 4;
    for (int it = 0; it < nIter; ++it) {
        cp_wait0();
        __syncthreads();
        const int buf = it & 1;
        if (it + 1 < nIter) {
            load_stage(buf ^ 1, (it + 1) << 4);
            cp_commit();
        }
        const float* sA = &As[buf][0];
        const float* sB = &Bs[buf][0];

        #pragma unroll
        for (int ks = 0; ks < 2; ks++) {
            const int kc = ks * 8;
            uint32_t af[4][4];
            #pragma unroll
            for (int mt = 0; mt < 4; mt++) {
                const float* ap = sA + (wm + mt * 16 + (lane >> 2)) * 20 + kc + (lane & 3);
                af[mt][0] = f2tf32(ap[0]);
                af[mt][1] = f2tf32(ap[8 * 20]);
                af[mt][2] = f2tf32(ap[4]);
                af[mt][3] = f2tf32(ap[8 * 20 + 4]);
            }
            uint32_t bf[4][2];
            #pragma unroll
            for (int nt = 0; nt < 4; nt++) {
                const float* bp = sB + (kc + (lane & 3)) * 136 + wn + nt * 8 + (lane >> 2);
                bf[nt][0] = f2tf32(bp[0]);
                bf[nt][1] = f2tf32(bp[4 * 136]);
            }
            #pragma unroll
            for (int mt = 0; mt < 4; mt++)
                #pragma unroll
                for (int nt = 0; nt < 4; nt++)
                    mma_tf32(acc[mt][nt], af[mt], bf[nt]);
        }
        __syncthreads();
    }

    // Epilogue: c0,c1 at (row, col..col+1); c2,c3 at (row+8, ...)
    #pragma unroll
    for (int mt = 0; mt < 4; mt++) {
        const int r0 = bm + wm + mt * 16 + (lane >> 2);
        #pragma unroll
        for (int nt = 0; nt < 4; nt++) {
            const int c = bn + wn + nt * 8 + (lane & 3) * 2;
            float b0 = bias[c], b1 = bias[c + 1];
            float2 v0 = make_float2(acc[mt][nt][0] + b0, acc[mt][nt][1] + b1);
            float2 v1 = make_float2(acc[mt][nt][2] + b0, acc[mt][nt][3] + b1);
            if (HAS_RES) {
                float2 r0v = *(const float2*)(Res + (size_t)r0 * N + c);
                float2 r1v = *(const float2*)(Res + (size_t)(r0 + 8) * N + c);
                v0.x += r0v.x; v0.y += r0v.y;
                v1.x += r1v.x; v1.y += r1v.y;
            }
            *(float2*)(C + (size_t)r0 * N + c)       = v0;
            *(float2*)(C + (size_t)(r0 + 8) * N + c) = v1;
        }
    }
}

// ---------------------------------------------------------------------------
// LayerNorm over D=1024. One block (256 threads) per row, float4 per thread.
// ---------------------------------------------------------------------------
__global__ __launch_bounds__(256) void ln_kernel(
    const float* __restrict__ in, const float* __restrict__ sc,
    const float* __restrict__ bi, float* __restrict__ out)
{
    const int row = blockIdx.x;
    const int t = threadIdx.x;
    const float4* x4 = (const float4*)(in + (size_t)row * 1024);
    float4 v = x4[t];
    float s  = v.x + v.y + v.z + v.w;
    float ss = v.x * v.x + v.y * v.y + v.z * v.z + v.w * v.w;
    #pragma unroll
    for (int o = 16; o; o >>= 1) {
        s  += __shfl_xor_sync(0xffffffffu, s,  o);
        ss += __shfl_xor_sync(0xffffffffu, ss, o);
    }
    __shared__ float sred[8], ssred[8];
    if ((t & 31) == 0) { sred[t >> 5] = s; ssred[t >> 5] = ss; }
    __syncthreads();
    float tot = 0.f, tots = 0.f;
    #pragma unroll
    for (int w = 0; w < 8; w++) { tot += sred[w]; tots += ssred[w]; }
    const float mean = tot * (1.f / 1024.f);
    const float var  = tots * (1.f / 1024.f) - mean * mean;
    const float inv  = rsqrtf(var + EPSF);
    float4 sv = ((const float4*)sc)[t];
    float4 bv = ((const float4*)bi)[t];
    float4 o4;
    o4.x = (v.x - mean) * inv * sv.x + bv.x;
    o4.y = (v.y - mean) * inv * sv.y + bv.y;
    o4.z = (v.z - mean) * inv * sv.z + bv.z;
    o4.w = (v.w - mean) * inv * sv.w + bv.w;
    ((float4*)(out + (size_t)row * 1024))[t] = o4;
}

// ---------------------------------------------------------------------------
// QK-norm: LayerNorm over DH=64 with (H,DH) scale/bias. One warp per (b,s,h).
// ---------------------------------------------------------------------------
__global__ __launch_bounds__(256) void qknorm_kernel(
    float* __restrict__ q, const float* __restrict__ sc, const float* __restrict__ bi)
{
    const int gw   = (blockIdx.x * 256 + threadIdx.x) >> 5;
    const int lane = threadIdx.x & 31;
    const int h  = gw & 15;
    const int bs = gw >> 4;
    float* p = q + (size_t)bs * 1024 + h * 64;
    float2 v = *(float2*)(p + lane * 2);
    float s  = v.x + v.y;
    float ss = v.x * v.x + v.y * v.y;
    #pragma unroll
    for (int o = 16; o; o >>= 1) {
        s  += __shfl_xor_sync(0xffffffffu, s,  o);
        ss += __shfl_xor_sync(0xffffffffu, ss, o);
    }
    const float mean = s * (1.f / 64.f);
    const float var  = ss * (1.f / 64.f) - mean * mean;
    const float inv  = rsqrtf(var + EPSF);
    const float* scp = sc + h * 64;
    const float* bip = bi + h * 64;
    v.x = (v.x - mean) * inv * scp[lane * 2 + 0] + bip[lane * 2 + 0];
    v.y = (v.y - mean) * inv * scp[lane * 2 + 1] + bip[lane * 2 + 1];
    *(float2*)(p + lane * 2) = v;
}

// ---------------------------------------------------------------------------
// Scores: S[b,h,q,t] = (q . k) / sqrt(64).  NT batched GEMM, 64x64 tile, K=64.
// ---------------------------------------------------------------------------
__global__ __launch_bounds__(256) void score_gemm(
    const float* __restrict__ q, const float* __restrict__ k, float* __restrict__ out)
{
    __shared__ float Qs[64][65];
    __shared__ float Ks[64][65];
    const int bh = blockIdx.z;
    const int b = bh >> 4, h = bh & 15;
    const float* qb = q + ((size_t)b * 1024 + blockIdx.x * 64) * 1024 + h * 64;
    const float* kb = k + ((size_t)b * 1024 + blockIdx.y * 64) * 1024 + h * 64;
    const int t = threadIdx.x;
    #pragma unroll
    for (int i = 0; i < 4; i++) {
        const int idx = t + 256 * i;
        const int row = idx >> 4;
        const int c4  = (idx & 15) << 2;
        float4 qv = *(const float4*)(qb + (size_t)row * 1024 + c4);
        float4 kv = *(const float4*)(kb + (size_t)row * 1024 + c4);
        Qs[c4 + 0][row] = qv.x; Qs[c4 + 1][row] = qv.y;
        Qs[c4 + 2][row] = qv.z; Qs[c4 + 3][row] = qv.w;
        Ks[c4 + 0][row] = kv.x; Ks[c4 + 1][row] = kv.y;
        Ks[c4 + 2][row] = kv.z; Ks[c4 + 3][row] = kv.w;
    }
    __syncthreads();
    const int tx = t & 15, ty = t >> 4;
    float acc[4][4] = {};
    #pragma unroll 8
    for (int d = 0; d < 64; ++d) {
        float qf[4], kf[4];
        #pragma unroll
        for (int i = 0; i < 4; i++) {
            qf[i] = Qs[d][(ty << 2) + i];
            kf[i] = Ks[d][(tx << 2) + i];
        }
        #pragma unroll
        for (int i = 0; i < 4; i++)
            #pragma unroll
            for (int j = 0; j < 4; j++)
                acc[i][j] += qf[i] * kf[j];
    }
    float* ob = out + ((size_t)bh << 20) + (size_t)(blockIdx.x * 64) * 1024 + blockIdx.y * 64;
    #pragma unroll
    for (int i = 0; i < 4; i++)
        #pragma unroll
        for (int j = 0; j < 4; j++)
            ob[(size_t)((ty << 2) + i) * 1024 + (tx << 2) + j] = acc[i][j] * 0.125f;
}

// ---------------------------------------------------------------------------
// Row softmax over 1024 (in-place).
// ---------------------------------------------------------------------------
__global__ __launch_bounds__(256) void softmax_kernel(float* __restrict__ s)
{
    const size_t row = blockIdx.x;
    float4* p = (float4*)(s + row * 1024);
    const int t = threadIdx.x;
    float4 v = p[t];
    float m = fmaxf(fmaxf(v.x, v.y), fmaxf(v.z, v.w));
    #pragma unroll
    for (int o = 16; o; o >>= 1) m = fmaxf(m, __shfl_xor_sync(0xffffffffu, m, o));
    __shared__ float redm[8], reds[8];
    if ((t & 31) == 0) redm[t >> 5] = m;
    __syncthreads();
    float mm = redm[0];
    #pragma unroll
    for (int w = 1; w < 8; w++) mm = fmaxf(mm, redm[w]);
    v.x = __expf(v.x - mm); v.y = __expf(v.y - mm);
    v.z = __expf(v.z - mm); v.w = __expf(v.w - mm);
    float sum = v.x + v.y + v.z + v.w;
    #pragma unroll
    for (int o = 16; o; o >>= 1) sum += __shfl_xor_sync(0xffffffffu, sum, o);
    if ((t & 31) == 0) reds[t >> 5] = sum;
    __syncthreads();
    float tot = 0.f;
    #pragma unroll
    for (int w = 0; w < 8; w++) tot += reds[w];
    const float inv = 1.f / tot;
    v.x *= inv; v.y *= inv; v.z *= inv; v.w *= inv;
    p[t] = v;
}

// ---------------------------------------------------------------------------
// attn @ V: NN batched GEMM, 64x64 tile, BK=32, K=1024.
// ---------------------------------------------------------------------------
__global__ __launch_bounds__(256) void av_gemm(
    const float* __restrict__ attn, const float* __restrict__ v, float* __restrict__ out)
{
    __shared__ float As[64][33];
    __shared__ float Bs[32][65];
    const int bh = blockIdx.y;
    const int b = bh >> 4, h = bh & 15;
    const float* ab = attn + ((size_t)bh << 20) + (size_t)blockIdx.x * 64 * 1024;
    const float* vb = v + (size_t)b * 1024 * 1024 + h * 64;
    const int t = threadIdx.x;
    const int tx = t & 15, ty = t >> 4;
    float acc[4][4] = {};
    for (int k0 = 0; k0 < 1024; k0 += 32) {
        #pragma unroll
        for (int i = 0; i < 2; i++) {
            const int idx = t + 256 * i;
            const int ar  = idx >> 3;
            const int ac4 = (idx & 7) << 2;
            float4 a4 = *(const float4*)(ab + (size_t)ar * 1024 + k0 + ac4);
            As[ar][ac4 + 0] = a4.x; As[ar][ac4 + 1] = a4.y;
            As[ar][ac4 + 2] = a4.z; As[ar][ac4 + 3] = a4.w;
            const int br  = idx >> 4;
            const int bc4 = (idx & 15) << 2;
            float4 b4 = *(const float4*)(vb + (size_t)(k0 + br) * 1024 + bc4);
            Bs[br][bc4 + 0] = b4.x; Bs[br][bc4 + 1] = b4.y;
            Bs[br][bc4 + 2] = b4.z; Bs[br][bc4 + 3] = b4.w;
        }
        __syncthreads();
        #pragma unroll 8
        for (int kk = 0; kk < 32; ++kk) {
            float a[4], bb[4];
            #pragma unroll
            for (int i = 0; i < 4; i++) {
                a[i]  = As[(ty << 2) + i][kk];
                bb[i] = Bs[kk][(tx << 2) + i];
            }
            #pragma unroll
            for (int i = 0; i < 4; i++)
                #pragma unroll
                for (int j = 0; j < 4; j++)
                    acc[i][j] += a[i] * bb[j];
        }
        __syncthreads();
    }
    float* ob = out + (size_t)b * 1024 * 1024 + (size_t)blockIdx.x * 64 * 1024 + h * 64;
    #pragma unroll
    for (int i = 0; i < 4; i++)
        #pragma unroll
        for (int j = 0; j < 4; j++)
            ob[(size_t)((ty << 2) + i) * 1024 + (tx << 2) + j] = acc[i][j];
}

// ---------------------------------------------------------------------------
// GeGLU: g1 <- g1 * gelu_tanh(g2).
// ---------------------------------------------------------------------------
__device__ __forceinline__ float gelu_t(float x)
{
    return 0.5f * x * (1.f + tanhf(0.7978845608028654f * (x + 0.044715f * x * x * x)));
}

__global__ __launch_bounds__(256) void geglu_kernel(
    float* __restrict__ g1, const float* __restrict__ g2)
{
    const size_t i = (size_t)blockIdx.x * 256 + threadIdx.x;
    float4 a = ((const float4*)g1)[i];
    float4 c = ((const float4*)g2)[i];
    a.x *= gelu_t(c.x);
    a.y *= gelu_t(c.y);
    a.z *= gelu_t(c.z);
    a.w *= gelu_t(c.w);
    ((float4*)g1)[i] = a;
}

// ---------------------------------------------------------------------------
// Launch
// ---------------------------------------------------------------------------
extern "C" void kernel_launch(void* const* d_in, const int* in_sizes, int n_in,
                              void* d_out, int out_size)
{
    (void)in_sizes; (void)n_in; (void)out_size;
    const float* x     = (const float*)d_in[0];
    const float* ln1_s = (const float*)d_in[2];
    const float* ln1_b = (const float*)d_in[3];
    const float* Wq    = (const float*)d_in[4];
    const float* bq    = (const float*)d_in[5];
    const float* Wk    = (const float*)d_in[6];
    const float* bk    = (const float*)d_in[7];
    const float* Wv    = (const float*)d_in[8];
    const float* bv    = (const float*)d_in[9];
    const float* qn_s  = (const float*)d_in[10];
    const float* qn_b  = (const float*)d_in[11];
    const float* kn_s  = (const float*)d_in[12];
    const float* kn_b  = (const float*)d_in[13];
    const float* Wo    = (const float*)d_in[14];
    const float* bo    = (const float*)d_in[15];
    const float* ln2_s = (const float*)d_in[16];
    const float* ln2_b = (const float*)d_in[17];
    const float* W1    = (const float*)d_in[18];
    const float* b1    = (const float*)d_in[19];
    const float* W2    = (const float*)d_in[20];
    const float* b2    = (const float*)d_in[21];
    const float* W3    = (const float*)d_in[22];
    const float* b3    = (const float*)d_in[23];

    float *xn, *q, *k, *v, *res, *big;
    cudaGetSymbolAddress((void**)&xn,  g_xn);
    cudaGetSymbolAddress((void**)&q,   g_q);
    cudaGetSymbolAddress((void**)&k,   g_k);
    cudaGetSymbolAddress((void**)&v,   g_v);
    cudaGetSymbolAddress((void**)&res, g_res);
    cudaGetSymbolAddress((void**)&big, g_big);

    float* out = (float*)d_out;

    // 1. LN1
    ln_kernel<<<4096, 256>>>(x, ln1_s, ln1_b, xn);

    // 2-4. QKV projections  (M=4096, N=1024, K=1024)
    dim3 gqkv(1024 / 128, 4096 / 128);
    gemm_tf32<false><<<gqkv, 256>>>(xn, Wq, bq, nullptr, q, 1024, 1024);
    gemm_tf32<false><<<gqkv, 256>>>(xn, Wk, bk, nullptr, k, 1024, 1024);
    gemm_tf32<false><<<gqkv, 256>>>(xn, Wv, bv, nullptr, v, 1024, 1024);

    // 5-6. QK-norm
    qknorm_kernel<<<8192, 256>>>(q, qn_s, qn_b);
    qknorm_kernel<<<8192, 256>>>(k, kn_s, kn_b);

    // 7. scores = q k^T / sqrt(DH)
    score_gemm<<<dim3(16, 16, 64), 256>>>(q, k, big);

    // 8. softmax over keys
    softmax_kernel<<<65536, 256>>>(big);

    // 9. attn @ V -> attn_out (reuse q)
    av_gemm<<<dim3(16, 64), 256>>>(big, v, q);

    // 10. O projection + residual with input x
    gemm_tf32<true><<<gqkv, 256>>>(q, Wo, bo, x, res, 1024, 1024);

    // 11. LN2 (reuse xn)
    ln_kernel<<<4096, 256>>>(res, ln2_s, ln2_b, xn);

    // 12-13. FFN up projections (M=4096, N=4096, K=1024)
    dim3 gffn(4096 / 128, 4096 / 128);
    float* h1 = big;
    float* h2 = big + (size_t)16777216;
    gemm_tf32<false><<<gffn, 256>>>(xn, W1, b1, nullptr, h1, 4096, 1024);
    gemm_tf32<false><<<gffn, 256>>>(xn, W2, b2, nullptr, h2, 4096, 1024);

    // 14. GeGLU
    geglu_kernel<<<16384, 256>>>(h1, h2);

    // 15. Down projection + residual -> d_out  (M=4096, N=1024, K=4096)
    dim3 gout(1024 / 128, 4096 / 128);
    gemm_tf32<true><<<gout, 256>>>(h1, W3, b3, res, out, 1024, 4096);
}

// round 3
// speedup vs baseline: 2.6511x; 1.2411x over previous
#include <cuda_runtime.h>
#include <math.h>
#include <stdint.h>

#define EPSF 1e-6f

// Problem constants: B=4, S=1024, D=1024, H=16, DH=64, F=4096, M=B*S=4096
__device__ float g_xn [4096 * 1024];        // LN output (rounded tf32)
__device__ float g_q  [4096 * 1024];        // q / attn_out
__device__ float g_k  [4096 * 1024];
__device__ float g_v  [4096 * 1024];
__device__ float g_res[4096 * 1024];        // residual after attention block
__device__ float g_big[64 * 1024 * 1024];   // scores [B,H,S,S]; later h1/h2
__device__ float g_wt [16 * 1024 * 1024];   // transposed+rounded weights (64MB)
__device__ float g_vt [4 * 1024 * 1024];    // v transposed per batch [b][d][s]

// ---------------------------------------------------------------------------
// Helpers
// ---------------------------------------------------------------------------
__device__ __forceinline__ void cp_async16(uint32_t dst, const void* src)
{
    asm volatile("cp.async.cg.shared.global [%0], [%1], 16;\n" :: "r"(dst), "l"(src));
}
__device__ __forceinline__ void cp_commit() { asm volatile("cp.async.commit_group;\n"); }
__device__ __forceinline__ void cp_wait0()  { asm volatile("cp.async.wait_group 0;\n"); }

__device__ __forceinline__ float tf32r(float x)
{
    uint32_t r;
    asm("cvt.rna.tf32.f32 %0, %1;\n" : "=r"(r) : "f"(x));
    return __uint_as_float(r);
}
__device__ __forceinline__ uint32_t smem_u32(const void* p)
{
    uint32_t a;
    asm("{ .reg .u64 t; cvta.to.shared.u64 t, %1; cvt.u32.u64 %0, t; }" : "=r"(a) : "l"(p));
    return a;
}
__device__ __forceinline__ void ldsm4(uint32_t& r0, uint32_t& r1, uint32_t& r2, uint32_t& r3,
                                      uint32_t a)
{
    asm volatile("ldmatrix.sync.aligned.m8n8.x4.shared.b16 {%0,%1,%2,%3}, [%4];"
                 : "=r"(r0), "=r"(r1), "=r"(r2), "=r"(r3) : "r"(a));
}
__device__ __forceinline__ void mma_tf32(float c[4], const uint32_t a[4], const uint32_t b[2])
{
    asm volatile(
        "mma.sync.aligned.m16n8k8.row.col.f32.tf32.tf32.f32 "
        "{%0,%1,%2,%3}, {%4,%5,%6,%7}, {%8,%9}, {%0,%1,%2,%3};\n"
        : "+f"(c[0]), "+f"(c[1]), "+f"(c[2]), "+f"(c[3])
        : "r"(a[0]), "r"(a[1]), "r"(a[2]), "r"(a[3]), "r"(b[0]), "r"(b[1]));
}

// ---------------------------------------------------------------------------
// Transpose + tf32-round: in[R][C] -> out[C][R], batched over blockIdx.z.
// ---------------------------------------------------------------------------
__global__ __launch_bounds__(256) void trans_round(
    const float* __restrict__ in, float* __restrict__ out, int R, int C)
{
    __shared__ float tile[32][33];
    const size_t zoff = (size_t)blockIdx.z * R * C;
    in += zoff; out += zoff;
    const int c0 = blockIdx.x * 32, r0 = blockIdx.y * 32;
    const int tx = threadIdx.x & 31, ty = threadIdx.x >> 5;
    #pragma unroll
    for (int i = 0; i < 4; i++)
        tile[ty + 8 * i][tx] = in[(size_t)(r0 + ty + 8 * i) * C + c0 + tx];
    __syncthreads();
    #pragma unroll
    for (int i = 0; i < 4; i++)
        out[(size_t)(c0 + ty + 8 * i) * R + r0 + tx] = tf32r(tile[tx][ty + 8 * i]);
}

// ---------------------------------------------------------------------------
// Unified tensor-core GEMM. BM=128, BK=16, cp.async double-buffer, ldmatrix
// fragment loads. Data must be pre-rounded to tf32. B operand stored n-major
// (row = n, stride ldb, contiguous in k).
// MODE 0: dense C=A@B+bias                (BN=128)
// MODE 1: dense C=A@B+bias+Res           (BN=128)
// MODE 2: score: per (b,h) Q@K^T * 0.125 (BN=128, z=bh)
// MODE 3: av:    per (b,h) attn@vT, round(out) (BN=64, z=bh)
// ---------------------------------------------------------------------------
template <int MODE>
__global__ __launch_bounds__(256) void gemm_mma(
    const float* __restrict__ A, const float* __restrict__ B,
    const float* __restrict__ bias, const float* __restrict__ Res,
    float* __restrict__ C, int N, int K, int lda, int ldb, int ldc)
{
    constexpr int BN = (MODE == 3) ? 64 : 128;
    constexpr int MT = (MODE == 3) ? 2 : 4;

    __shared__ alignas(16) float As[2][128 * 20];
    __shared__ alignas(16) float Bs[2][BN * 20];

    const int t    = threadIdx.x;
    const int lane = t & 31;
    const int warp = t >> 5;
    const size_t m0 = (size_t)blockIdx.y * 128;
    const size_t n0 = (size_t)blockIdx.x * BN;

    int wm, wn;
    if (MODE == 3) { wm = (warp >> 1) * 32; wn = (warp & 1) * 32; }
    else           { wm = (warp >> 2) * 64; wn = (warp & 3) * 32; }

    const float* Ab;
    const float* Bb;
    float* Cb;
    const float* Rb = nullptr;
    const float* biasb = nullptr;
    if (MODE <= 1) {
        Ab = A + m0 * lda;
        Bb = B + n0 * ldb;
        Cb = C + m0 * ldc + n0;
        biasb = bias + n0;
        if (MODE == 1) Rb = Res + m0 * ldc + n0;
    } else if (MODE == 2) {
        const int z = blockIdx.z, b = z >> 4, h = z & 15;
        Ab = A + ((size_t)b << 20) + m0 * 1024 + h * 64;
        Bb = B + ((size_t)b << 20) + n0 * 1024 + h * 64;
        Cb = C + ((size_t)z << 20) + m0 * 1024 + n0;
    } else {
        const int z = blockIdx.z, b = z >> 4, h = z & 15;
        Ab = A + ((size_t)z << 20) + m0 * 1024;
        Bb = B + ((size_t)b << 20) + (size_t)h * 64 * 1024;
        Cb = C + ((size_t)b << 20) + m0 * 1024 + h * 64;
    }

    // cp.async maps
    const int a_row = t >> 1, a_off = (t & 1) * 8;
    const float* Aldg = Ab + (size_t)a_row * lda + a_off;
    int b_row, b_off;
    if (BN == 128) { b_row = t >> 1; b_off = (t & 1) * 8; }
    else           { b_row = t >> 2; b_off = (t & 3) * 4; }
    const float* Bldg = Bb + (size_t)b_row * ldb + b_off;

    const uint32_t sA = smem_u32(&As[0][0]);
    const uint32_t sB = smem_u32(&Bs[0][0]);
    const uint32_t dA = sA + (uint32_t)(a_row * 20 + a_off) * 4;
    const uint32_t dB = sB + (uint32_t)(b_row * 20 + b_off) * 4;
    constexpr uint32_t A_STAGE = 128 * 20 * 4;
    constexpr uint32_t B_STAGE = BN * 20 * 4;

    // ldmatrix lane addresses
    const int lq = lane >> 3, lr = lane & 7;
    uint32_t aAddr[MT], bAddr[2];
    #pragma unroll
    for (int mt = 0; mt < MT; mt++) {
        const int row = wm + mt * 16 + ((lq & 1) << 3) + lr;
        const int col = (lq >> 1) << 2;
        aAddr[mt] = sA + (uint32_t)(row * 20 + col) * 4;
    }
    #pragma unroll
    for (int p = 0; p < 2; p++) {
        const int n = wn + ((p << 1) + (lq >> 1)) * 8 + lr;
        const int col = (lq & 1) << 2;
        bAddr[p] = sB + (uint32_t)(n * 20 + col) * 4;
    }

    float acc[MT][4][4];
    #pragma unroll
    for (int mt = 0; mt < MT; mt++)
        #pragma unroll
        for (int nt = 0; nt < 4; nt++)
            #pragma unroll
            for (int i = 0; i < 4; i++) acc[mt][nt][i] = 0.f;

    auto load_stage = [&](int buf, int k0) {
        cp_async16(dA + buf * A_STAGE, Aldg + k0);
        cp_async16(dA + buf * A_STAGE + 16, Aldg + k0 + 4);
        cp_async16(dB + buf * B_STAGE, Bldg + k0);
        if (BN == 128) cp_async16(dB + buf * B_STAGE + 16, Bldg + k0 + 4);
    };

    load_stage(0, 0);
    cp_commit();

    const int nIter = K >> 4;
    for (int it = 0; it < nIter; ++it) {
        cp_wait0();
        __syncthreads();
        const int buf = it & 1;
        if (it + 1 < nIter) {
            load_stage(buf ^ 1, (it + 1) << 4);
            cp_commit();
        }
        const uint32_t aOff = buf * A_STAGE;
        const uint32_t bOff = buf * B_STAGE;
        #pragma unroll
        for (int ks = 0; ks < 2; ks++) {
            const uint32_t kB = ks * 32;   // 8 floats
            uint32_t af[MT][4];
            #pragma unroll
            for (int mt = 0; mt < MT; mt++)
                ldsm4(af[mt][0], af[mt][1], af[mt][2], af[mt][3], aAddr[mt] + aOff + kB);
            uint32_t bf[4][2];
            #pragma unroll
            for (int p = 0; p < 2; p++)
                ldsm4(bf[2 * p][0], bf[2 * p][1], bf[2 * p + 1][0], bf[2 * p + 1][1],
                      bAddr[p] + bOff + kB);
            #pragma unroll
            for (int mt = 0; mt < MT; mt++)
                #pragma unroll
                for (int nt = 0; nt < 4; nt++)
                    mma_tf32(acc[mt][nt], af[mt], bf[nt]);
        }
        __syncthreads();
    }

    // Epilogue
    #pragma unroll
    for (int mt = 0; mt < MT; mt++) {
        const int r0 = wm + mt * 16 + (lane >> 2);
        #pragma unroll
        for (int nt = 0; nt < 4; nt++) {
            const int c = wn + nt * 8 + (lane & 3) * 2;
            float2 v0 = make_float2(acc[mt][nt][0], acc[mt][nt][1]);
            float2 v1 = make_float2(acc[mt][nt][2], acc[mt][nt][3]);
            if (MODE <= 1) {
                const float b0 = biasb[c], b1 = biasb[c + 1];
                v0.x += b0; v0.y += b1; v1.x += b0; v1.y += b1;
                if (MODE == 1) {
                    float2 ra = *(const float2*)(Rb + (size_t)r0 * ldc + c);
                    float2 rb = *(const float2*)(Rb + (size_t)(r0 + 8) * ldc + c);
                    v0.x += ra.x; v0.y += ra.y; v1.x += rb.x; v1.y += rb.y;
                }
            } else if (MODE == 2) {
                v0.x *= 0.125f; v0.y *= 0.125f; v1.x *= 0.125f; v1.y *= 0.125f;
            } else {
                v0.x = tf32r(v0.x); v0.y = tf32r(v0.y);
                v1.x = tf32r(v1.x); v1.y = tf32r(v1.y);
            }
            *(float2*)(Cb + (size_t)r0 * ldc + c)       = v0;
            *(float2*)(Cb + (size_t)(r0 + 8) * ldc + c) = v1;
        }
    }
}

// ---------------------------------------------------------------------------
// LayerNorm over D=1024, tf32-rounded output.
// ---------------------------------------------------------------------------
__global__ __launch_bounds__(256) void ln_kernel(
    const float* __restrict__ in, const float* __restrict__ sc,
    const float* __restrict__ bi, float* __restrict__ out)
{
    const int row = blockIdx.x;
    const int t = threadIdx.x;
    const float4* x4 = (const float4*)(in + (size_t)row * 1024);
    float4 v = x4[t];
    float s  = v.x + v.y + v.z + v.w;
    float ss = v.x * v.x + v.y * v.y + v.z * v.z + v.w * v.w;
    #pragma unroll
    for (int o = 16; o; o >>= 1) {
        s  += __shfl_xor_sync(0xffffffffu, s,  o);
        ss += __shfl_xor_sync(0xffffffffu, ss, o);
    }
    __shared__ float sred[8], ssred[8];
    if ((t & 31) == 0) { sred[t >> 5] = s; ssred[t >> 5] = ss; }
    __syncthreads();
    float tot = 0.f, tots = 0.f;
    #pragma unroll
    for (int w = 0; w < 8; w++) { tot += sred[w]; tots += ssred[w]; }
    const float mean = tot * (1.f / 1024.f);
    const float var  = tots * (1.f / 1024.f) - mean * mean;
    const float inv  = rsqrtf(var + EPSF);
    float4 sv = ((const float4*)sc)[t];
    float4 bv = ((const float4*)bi)[t];
    float4 o4;
    o4.x = tf32r((v.x - mean) * inv * sv.x + bv.x);
    o4.y = tf32r((v.y - mean) * inv * sv.y + bv.y);
    o4.z = tf32r((v.z - mean) * inv * sv.z + bv.z);
    o4.w = tf32r((v.w - mean) * inv * sv.w + bv.w);
    ((float4*)(out + (size_t)row * 1024))[t] = o4;
}

// ---------------------------------------------------------------------------
// QK-norm over DH=64, (H,DH) scale/bias, in-place, tf32-rounded.
// ---------------------------------------------------------------------------
__global__ __launch_bounds__(256) void qknorm_kernel(
    float* __restrict__ q, const float* __restrict__ sc, const float* __restrict__ bi)
{
    const int gw   = (blockIdx.x * 256 + threadIdx.x) >> 5;
    const int lane = threadIdx.x & 31;
    const int h  = gw & 15;
    const int bs = gw >> 4;
    float* p = q + (size_t)bs * 1024 + h * 64;
    float2 v = *(float2*)(p + lane * 2);
    float s  = v.x + v.y;
    float ss = v.x * v.x + v.y * v.y;
    #pragma unroll
    for (int o = 16; o; o >>= 1) {
        s  += __shfl_xor_sync(0xffffffffu, s,  o);
        ss += __shfl_xor_sync(0xffffffffu, ss, o);
    }
    const float mean = s * (1.f / 64.f);
    const float var  = ss * (1.f / 64.f) - mean * mean;
    const float inv  = rsqrtf(var + EPSF);
    const float* scp = sc + h * 64;
    const float* bip = bi + h * 64;
    v.x = tf32r((v.x - mean) * inv * scp[lane * 2 + 0] + bip[lane * 2 + 0]);
    v.y = tf32r((v.y - mean) * inv * scp[lane * 2 + 1] + bip[lane * 2 + 1]);
    *(float2*)(p + lane * 2) = v;
}

// ---------------------------------------------------------------------------
// Row softmax over 1024 (in-place), tf32-rounded output.
// ---------------------------------------------------------------------------
__global__ __launch_bounds__(256) void softmax_kernel(float* __restrict__ s)
{
    const size_t row = blockIdx.x;
    float4* p = (float4*)(s + row * 1024);
    const int t = threadIdx.x;
    float4 v = p[t];
    float m = fmaxf(fmaxf(v.x, v.y), fmaxf(v.z, v.w));
    #pragma unroll
    for (int o = 16; o; o >>= 1) m = fmaxf(m, __shfl_xor_sync(0xffffffffu, m, o));
    __shared__ float redm[8], reds[8];
    if ((t & 31) == 0) redm[t >> 5] = m;
    __syncthreads();
    float mm = redm[0];
    #pragma unroll
    for (int w = 1; w < 8; w++) mm = fmaxf(mm, redm[w]);
    v.x = __expf(v.x - mm); v.y = __expf(v.y - mm);
    v.z = __expf(v.z - mm); v.w = __expf(v.w - mm);
    float sum = v.x + v.y + v.z + v.w;
    #pragma unroll
    for (int o = 16; o; o >>= 1) sum += __shfl_xor_sync(0xffffffffu, sum, o);
    if ((t & 31) == 0) reds[t >> 5] = sum;
    __syncthreads();
    float tot = 0.f;
    #pragma unroll
    for (int w = 0; w < 8; w++) tot += reds[w];
    const float inv = 1.f / tot;
    v.x = tf32r(v.x * inv); v.y = tf32r(v.y * inv);
    v.z = tf32r(v.z * inv); v.w = tf32r(v.w * inv);
    p[t] = v;
}

// ---------------------------------------------------------------------------
// GeGLU: g1 <- round(g1 * gelu_tanh(g2)).
// ---------------------------------------------------------------------------
__device__ __forceinline__ float gelu_t(float x)
{
    return 0.5f * x * (1.f + tanhf(0.7978845608028654f * (x + 0.044715f * x * x * x)));
}

__global__ __launch_bounds__(256) void geglu_kernel(
    float* __restrict__ g1, const float* __restrict__ g2)
{
    const size_t i = (size_t)blockIdx.x * 256 + threadIdx.x;
    float4 a = ((const float4*)g1)[i];
    float4 c = ((const float4*)g2)[i];
    a.x = tf32r(a.x * gelu_t(c.x));
    a.y = tf32r(a.y * gelu_t(c.y));
    a.z = tf32r(a.z * gelu_t(c.z));
    a.w = tf32r(a.w * gelu_t(c.w));
    ((float4*)g1)[i] = a;
}

// ---------------------------------------------------------------------------
// Launch
// ---------------------------------------------------------------------------
extern "C" void kernel_launch(void* const* d_in, const int* in_sizes, int n_in,
                              void* d_out, int out_size)
{
    (void)in_sizes; (void)n_in; (void)out_size;
    const float* x     = (const float*)d_in[0];
    const float* ln1_s = (const float*)d_in[2];
    const float* ln1_b = (const float*)d_in[3];
    const float* Wq    = (const float*)d_in[4];
    const float* bq    = (const float*)d_in[5];
    const float* Wk    = (const float*)d_in[6];
    const float* bk    = (const float*)d_in[7];
    const float* Wv    = (const float*)d_in[8];
    const float* bv    = (const float*)d_in[9];
    const float* qn_s  = (const float*)d_in[10];
    const float* qn_b  = (const float*)d_in[11];
    const float* kn_s  = (const float*)d_in[12];
    const float* kn_b  = (const float*)d_in[13];
    const float* Wo    = (const float*)d_in[14];
    const float* bo    = (const float*)d_in[15];
    const float* ln2_s = (const float*)d_in[16];
    const float* ln2_b = (const float*)d_in[17];
    const float* W1    = (const float*)d_in[18];
    const float* b1    = (const float*)d_in[19];
    const float* W2    = (const float*)d_in[20];
    const float* b2    = (const float*)d_in[21];
    const float* W3    = (const float*)d_in[22];
    const float* b3    = (const float*)d_in[23];

    float *xn, *q, *k, *v, *res, *big, *wt, *vt;
    cudaGetSymbolAddress((void**)&xn,  g_xn);
    cudaGetSymbolAddress((void**)&q,   g_q);
    cudaGetSymbolAddress((void**)&k,   g_k);
    cudaGetSymbolAddress((void**)&v,   g_v);
    cudaGetSymbolAddress((void**)&res, g_res);
    cudaGetSymbolAddress((void**)&big, g_big);
    cudaGetSymbolAddress((void**)&wt,  g_wt);
    cudaGetSymbolAddress((void**)&vt,  g_vt);

    float* out = (float*)d_out;
    const size_t MB1 = 1024 * 1024;
    float* wqt = wt;
    float* wkt = wt + 1 * MB1;
    float* wvt = wt + 2 * MB1;
    float* wot = wt + 3 * MB1;
    float* w1t = wt + 4 * MB1;
    float* w2t = wt + 8 * MB1;
    float* w3t = wt + 12 * MB1;

    // 0. weight transposes + tf32 rounding
    trans_round<<<dim3(32, 32), 256>>>(Wq, wqt, 1024, 1024);
    trans_round<<<dim3(32, 32), 256>>>(Wk, wkt, 1024, 1024);
    trans_round<<<dim3(32, 32), 256>>>(Wv, wvt, 1024, 1024);
    trans_round<<<dim3(32, 32), 256>>>(Wo, wot, 1024, 1024);
    trans_round<<<dim3(128, 32), 256>>>(W1, w1t, 1024, 4096);
    trans_round<<<dim3(128, 32), 256>>>(W2, w2t, 1024, 4096);
    trans_round<<<dim3(32, 128), 256>>>(W3, w3t, 4096, 1024);

    // 1. LN1 (rounded)
    ln_kernel<<<4096, 256>>>(x, ln1_s, ln1_b, xn);

    // 2-4. QKV projections (M=4096, N=1024, K=1024)
    dim3 gqkv(8, 32);
    gemm_mma<0><<<gqkv, 256>>>(xn, wqt, bq, nullptr, q, 1024, 1024, 1024, 1024, 1024);
    gemm_mma<0><<<gqkv, 256>>>(xn, wkt, bk, nullptr, k, 1024, 1024, 1024, 1024, 1024);
    gemm_mma<0><<<gqkv, 256>>>(xn, wvt, bv, nullptr, v, 1024, 1024, 1024, 1024, 1024);

    // 5-6. QK-norm (rounded)
    qknorm_kernel<<<8192, 256>>>(q, qn_s, qn_b);
    qknorm_kernel<<<8192, 256>>>(k, kn_s, kn_b);

    // 6b. v -> vT per batch (rounded)
    trans_round<<<dim3(32, 32, 4), 256>>>(v, vt, 1024, 1024);

    // 7. scores = q k^T / 8
    gemm_mma<2><<<dim3(8, 8, 64), 256>>>(q, k, nullptr, nullptr, big, 1024, 64, 1024, 1024, 1024);

    // 8. softmax (rounded)
    softmax_kernel<<<65536, 256>>>(big);

    // 9. attn @ V -> attn_out (reuse q, rounded)
    gemm_mma<3><<<dim3(1, 8, 64), 256>>>(big, vt, nullptr, nullptr, q, 64, 1024, 1024, 1024, 1024);

    // 10. O projection + residual
    gemm_mma<1><<<gqkv, 256>>>(q, wot, bo, x, res, 1024, 1024, 1024, 1024, 1024);

    // 11. LN2 (rounded)
    ln_kernel<<<4096, 256>>>(res, ln2_s, ln2_b, xn);

    // 12-13. FFN up (M=4096, N=4096, K=1024)
    dim3 gffn(32, 32);
    float* h1 = big;
    float* h2 = big + (size_t)16777216;
    gemm_mma<0><<<gffn, 256>>>(xn, w1t, b1, nullptr, h1, 4096, 1024, 1024, 1024, 4096);
    gemm_mma<0><<<gffn, 256>>>(xn, w2t, b2, nullptr, h2, 4096, 1024, 1024, 1024, 4096);

    // 14. GeGLU (rounds h1)
    geglu_kernel<<<16384, 256>>>(h1, h2);

    // 15. Down projection + residual -> d_out (M=4096, N=1024, K=4096)
    gemm_mma<1><<<dim3(8, 32), 256>>>(h1, w3t, b3, res, out, 1024, 4096, 4096, 4096, 1024);
}

// round 4
// speedup vs baseline: 2.8103x; 1.0601x over previous
#include <cuda_runtime.h>
#include <math.h>
#include <stdint.h>

#define EPSF 1e-6f

// Problem constants: B=4, S=1024, D=1024, H=16, DH=64, F=4096, M=B*S=4096
__device__ float g_xn [4096 * 1024];        // LN output (rounded tf32)
__device__ float g_q  [4096 * 1024];        // q / attn_out
__device__ float g_k  [4096 * 1024];
__device__ float g_v  [4096 * 1024];
__device__ float g_res[4096 * 1024];        // residual after attention block
__device__ float g_big[32 * 1024 * 1024];   // h1/h2 of FFN (128 MB)
__device__ float g_wt [16 * 1024 * 1024];   // transposed+rounded weights (64MB)
__device__ float g_vt [4 * 1024 * 1024];    // v transposed per batch [b][d][s]

// ---------------------------------------------------------------------------
// Helpers
// ---------------------------------------------------------------------------
__device__ __forceinline__ void cp_async16(uint32_t dst, const void* src)
{
    asm volatile("cp.async.cg.shared.global [%0], [%1], 16;\n" :: "r"(dst), "l"(src));
}
__device__ __forceinline__ void cp_commit() { asm volatile("cp.async.commit_group;\n"); }
__device__ __forceinline__ void cp_wait0()  { asm volatile("cp.async.wait_group 0;\n"); }

__device__ __forceinline__ float tf32r(float x)
{
    uint32_t r;
    asm("cvt.rna.tf32.f32 %0, %1;\n" : "=r"(r) : "f"(x));
    return __uint_as_float(r);
}
__device__ __forceinline__ uint32_t smem_u32(const void* p)
{
    uint32_t a;
    asm("{ .reg .u64 t; cvta.to.shared.u64 t, %1; cvt.u32.u64 %0, t; }" : "=r"(a) : "l"(p));
    return a;
}
__device__ __forceinline__ void ldsm4(uint32_t& r0, uint32_t& r1, uint32_t& r2, uint32_t& r3,
                                      uint32_t a)
{
    asm volatile("ldmatrix.sync.aligned.m8n8.x4.shared.b16 {%0,%1,%2,%3}, [%4];"
                 : "=r"(r0), "=r"(r1), "=r"(r2), "=r"(r3) : "r"(a));
}
__device__ __forceinline__ void mma_tf32(float c[4], const uint32_t a[4], const uint32_t b[2])
{
    asm volatile(
        "mma.sync.aligned.m16n8k8.row.col.f32.tf32.tf32.f32 "
        "{%0,%1,%2,%3}, {%4,%5,%6,%7}, {%8,%9}, {%0,%1,%2,%3};\n"
        : "+f"(c[0]), "+f"(c[1]), "+f"(c[2]), "+f"(c[3])
        : "r"(a[0]), "r"(a[1]), "r"(a[2]), "r"(a[3]), "r"(b[0]), "r"(b[1]));
}

// ---------------------------------------------------------------------------
// Transpose + tf32-round: in[R][C] -> out[C][R], batched over blockIdx.z.
// ---------------------------------------------------------------------------
__global__ __launch_bounds__(256) void trans_round(
    const float* __restrict__ in, float* __restrict__ out, int R, int C)
{
    __shared__ float tile[32][33];
    const size_t zoff = (size_t)blockIdx.z * R * C;
    in += zoff; out += zoff;
    const int c0 = blockIdx.x * 32, r0 = blockIdx.y * 32;
    const int tx = threadIdx.x & 31, ty = threadIdx.x >> 5;
    #pragma unroll
    for (int i = 0; i < 4; i++)
        tile[ty + 8 * i][tx] = in[(size_t)(r0 + ty + 8 * i) * C + c0 + tx];
    __syncthreads();
    #pragma unroll
    for (int i = 0; i < 4; i++)
        out[(size_t)(c0 + ty + 8 * i) * R + r0 + tx] = tf32r(tile[tx][ty + 8 * i]);
}

// ---------------------------------------------------------------------------
// Dense tensor-core GEMM (as round 3). MODE 0: +bias; MODE 1: +bias+Res.
// ---------------------------------------------------------------------------
template <int MODE>
__global__ __launch_bounds__(256) void gemm_mma(
    const float* __restrict__ A, const float* __restrict__ B,
    const float* __restrict__ bias, const float* __restrict__ Res,
    float* __restrict__ C, int N, int K, int lda, int ldb, int ldc)
{
    __shared__ alignas(16) float As[2][128 * 20];
    __shared__ alignas(16) float Bs[2][128 * 20];

    const int t    = threadIdx.x;
    const int lane = t & 31;
    const int warp = t >> 5;
    const size_t m0 = (size_t)blockIdx.y * 128;
    const size_t n0 = (size_t)blockIdx.x * 128;
    const int wm = (warp >> 2) * 64;
    const int wn = (warp & 3) * 32;

    const float* Ab = A + m0 * lda;
    const float* Bb = B + n0 * ldb;
    float* Cb = C + m0 * ldc + n0;
    const float* biasb = bias + n0;
    const float* Rb = (MODE == 1) ? (Res + m0 * ldc + n0) : nullptr;

    const int a_row = t >> 1, a_off = (t & 1) * 8;
    const float* Aldg = Ab + (size_t)a_row * lda + a_off;
    const float* Bldg = Bb + (size_t)a_row * ldb + a_off;

    const uint32_t sA = smem_u32(&As[0][0]);
    const uint32_t sB = smem_u32(&Bs[0][0]);
    const uint32_t dA = sA + (uint32_t)(a_row * 20 + a_off) * 4;
    const uint32_t dB = sB + (uint32_t)(a_row * 20 + a_off) * 4;
    constexpr uint32_t STAGE = 128 * 20 * 4;

    const int lq = lane >> 3, lr = lane & 7;
    uint32_t aAddr[4], bAddr[2];
    #pragma unroll
    for (int mt = 0; mt < 4; mt++)
        aAddr[mt] = sA + (uint32_t)((wm + mt * 16 + ((lq & 1) << 3) + lr) * 20 + ((lq >> 1) << 2)) * 4;
    #pragma unroll
    for (int p = 0; p < 2; p++)
        bAddr[p] = sB + (uint32_t)((wn + ((p << 1) + (lq >> 1)) * 8 + lr) * 20 + ((lq & 1) << 2)) * 4;

    float acc[4][4][4];
    #pragma unroll
    for (int mt = 0; mt < 4; mt++)
        #pragma unroll
        for (int nt = 0; nt < 4; nt++)
            #pragma unroll
            for (int i = 0; i < 4; i++) acc[mt][nt][i] = 0.f;

    auto load_stage = [&](int buf, int k0) {
        cp_async16(dA + buf * STAGE, Aldg + k0);
        cp_async16(dA + buf * STAGE + 16, Aldg + k0 + 4);
        cp_async16(dB + buf * STAGE, Bldg + k0);
        cp_async16(dB + buf * STAGE + 16, Bldg + k0 + 4);
    };

    load_stage(0, 0);
    cp_commit();

    const int nIter = K >> 4;
    for (int it = 0; it < nIter; ++it) {
        cp_wait0();
        __syncthreads();
        const int buf = it & 1;
        if (it + 1 < nIter) {
            load_stage(buf ^ 1, (it + 1) << 4);
            cp_commit();
        }
        const uint32_t off = buf * STAGE;
        #pragma unroll
        for (int ks = 0; ks < 2; ks++) {
            const uint32_t kB = ks * 32;
            uint32_t af[4][4];
            #pragma unroll
            for (int mt = 0; mt < 4; mt++)
                ldsm4(af[mt][0], af[mt][1], af[mt][2], af[mt][3], aAddr[mt] + off + kB);
            uint32_t bf[4][2];
            #pragma unroll
            for (int p = 0; p < 2; p++)
                ldsm4(bf[2 * p][0], bf[2 * p][1], bf[2 * p + 1][0], bf[2 * p + 1][1],
                      bAddr[p] + off + kB);
            #pragma unroll
            for (int mt = 0; mt < 4; mt++)
                #pragma unroll
                for (int nt = 0; nt < 4; nt++)
                    mma_tf32(acc[mt][nt], af[mt], bf[nt]);
        }
        __syncthreads();
    }

    #pragma unroll
    for (int mt = 0; mt < 4; mt++) {
        const int r0 = wm + mt * 16 + (lane >> 2);
        #pragma unroll
        for (int nt = 0; nt < 4; nt++) {
            const int c = wn + nt * 8 + (lane & 3) * 2;
            const float b0 = biasb[c], b1 = biasb[c + 1];
            float2 v0 = make_float2(acc[mt][nt][0] + b0, acc[mt][nt][1] + b1);
            float2 v1 = make_float2(acc[mt][nt][2] + b0, acc[mt][nt][3] + b1);
            if (MODE == 1) {
                float2 ra = *(const float2*)(Rb + (size_t)r0 * ldc + c);
                float2 rb = *(const float2*)(Rb + (size_t)(r0 + 8) * ldc + c);
                v0.x += ra.x; v0.y += ra.y; v1.x += rb.x; v1.y += rb.y;
            }
            *(float2*)(Cb + (size_t)r0 * ldc + c)       = v0;
            *(float2*)(Cb + (size_t)(r0 + 8) * ldc + c) = v1;
        }
    }
}

// ---------------------------------------------------------------------------
// Flash attention: per CTA one 128-row Q tile x one (b,h). Loops 8 key tiles
// of 128. Online softmax; P never hits gmem. Inputs q,k pre-rounded tf32;
// vt = rounded [b][d][s]. Output (attn out) tf32-rounded to g_q layout.
// smem: K[128][68] | Vt[64][132] | P[128][132]  (P doubles as Q staging)
// ---------------------------------------------------------------------------
#define FL_SMEM ((128 * 68 + 64 * 132 + 128 * 132) * 4)

__global__ __launch_bounds__(256) void flash_kernel(
    const float* __restrict__ q, const float* __restrict__ k,
    const float* __restrict__ vt, float* __restrict__ out)
{
    extern __shared__ float sm[];
    const uint32_t sKu = smem_u32(sm);
    const uint32_t sVu = sKu + 128 * 68 * 4;
    const uint32_t sPu = sVu + 64 * 132 * 4;
    float* sPf = sm + 128 * 68 + 64 * 132;

    const int t = threadIdx.x;
    const int lane = t & 31, warp = t >> 5;
    const int lq = lane >> 3, lr = lane & 7;
    const int bh = blockIdx.y, b = bh >> 4, h = bh & 15;
    const int q0 = blockIdx.x * 128;
    const int wm = warp * 16;

    const float* qb = q + ((size_t)b * 1024 + q0) * 1024 + h * 64;
    const float* kb = k + ((size_t)b << 20) + h * 64;
    const float* vb = vt + ((size_t)b << 20) + (size_t)h * 64 * 1024;

    // stage Q (stride 68) into P region
    {
        const int row = t >> 1, c0 = (t & 1) * 32;
        const uint32_t dst = sPu + (uint32_t)(row * 68 + c0) * 4;
        const float* src = qb + (size_t)row * 1024 + c0;
        #pragma unroll
        for (int i = 0; i < 8; i++) cp_async16(dst + i * 16, src + i * 4);
    }
    cp_commit(); cp_wait0(); __syncthreads();

    uint32_t qf[8][4];
    {
        const uint32_t a0 = sPu + (uint32_t)((wm + ((lq & 1) << 3) + lr) * 68 + ((lq >> 1) << 2)) * 4;
        #pragma unroll
        for (int ks = 0; ks < 8; ks++)
            ldsm4(qf[ks][0], qf[ks][1], qf[ks][2], qf[ks][3], a0 + ks * 32);
    }
    __syncthreads();

    float o[8][4];
    #pragma unroll
    for (int i = 0; i < 8; i++)
        #pragma unroll
        for (int j = 0; j < 4; j++) o[i][j] = 0.f;
    float m0 = -1e30f, m1 = -1e30f, l0 = 0.f, l1 = 0.f;

    const uint32_t aP = sPu + (uint32_t)((wm + ((lq & 1) << 3) + lr) * 132 + ((lq >> 1) << 2)) * 4;

    for (int it = 0; it < 8; ++it) {
        const int kt0 = it * 128;
        {   // K tile
            const int row = t >> 1, c0 = (t & 1) * 32;
            const uint32_t dst = sKu + (uint32_t)(row * 68 + c0) * 4;
            const float* src = kb + (size_t)(kt0 + row) * 1024 + c0;
            #pragma unroll
            for (int i = 0; i < 8; i++) cp_async16(dst + i * 16, src + i * 4);
        }
        {   // V^T tile
            const int row = t >> 2, c0 = (t & 3) * 32;
            const uint32_t dst = sVu + (uint32_t)(row * 132 + c0) * 4;
            const float* src = vb + (size_t)row * 1024 + kt0 + c0;
            #pragma unroll
            for (int i = 0; i < 8; i++) cp_async16(dst + i * 16, src + i * 4);
        }
        cp_commit(); cp_wait0(); __syncthreads();

        // scores: 16 rows x 128 keys per warp
        float s[16][4];
        #pragma unroll
        for (int i = 0; i < 16; i++)
            #pragma unroll
            for (int j = 0; j < 4; j++) s[i][j] = 0.f;
        #pragma unroll
        for (int ks = 0; ks < 8; ks++) {
            uint32_t bf[16][2];
            #pragma unroll
            for (int p = 0; p < 8; p++) {
                const uint32_t addr =
                    sKu + (uint32_t)((((p << 1) + (lq >> 1)) * 8 + lr) * 68 + ((lq & 1) << 2)) * 4
                        + ks * 32;
                ldsm4(bf[2 * p][0], bf[2 * p][1], bf[2 * p + 1][0], bf[2 * p + 1][1], addr);
            }
            #pragma unroll
            for (int nt = 0; nt < 16; nt++)
                mma_tf32(s[nt], qf[ks], bf[nt]);
        }

        // online softmax (scale 0.125)
        float c0v = -1e30f, c1v = -1e30f;
        #pragma unroll
        for (int nt = 0; nt < 16; nt++) {
            c0v = fmaxf(c0v, fmaxf(s[nt][0], s[nt][1]));
            c1v = fmaxf(c1v, fmaxf(s[nt][2], s[nt][3]));
        }
        c0v = fmaxf(c0v, __shfl_xor_sync(0xffffffffu, c0v, 1));
        c0v = fmaxf(c0v, __shfl_xor_sync(0xffffffffu, c0v, 2));
        c1v = fmaxf(c1v, __shfl_xor_sync(0xffffffffu, c1v, 1));
        c1v = fmaxf(c1v, __shfl_xor_sync(0xffffffffu, c1v, 2));
        const float m0n = fmaxf(m0, c0v * 0.125f);
        const float m1n = fmaxf(m1, c1v * 0.125f);
        const float cor0 = __expf(m0 - m0n);
        const float cor1 = __expf(m1 - m1n);
        m0 = m0n; m1 = m1n;
        float sum0 = 0.f, sum1 = 0.f;
        #pragma unroll
        for (int nt = 0; nt < 16; nt++) {
            float p0 = __expf(fmaf(0.125f, s[nt][0], -m0n));
            float p1 = __expf(fmaf(0.125f, s[nt][1], -m0n));
            float p2 = __expf(fmaf(0.125f, s[nt][2], -m1n));
            float p3 = __expf(fmaf(0.125f, s[nt][3], -m1n));
            sum0 += p0 + p1; sum1 += p2 + p3;
            s[nt][0] = tf32r(p0); s[nt][1] = tf32r(p1);
            s[nt][2] = tf32r(p2); s[nt][3] = tf32r(p3);
        }
        sum0 += __shfl_xor_sync(0xffffffffu, sum0, 1);
        sum0 += __shfl_xor_sync(0xffffffffu, sum0, 2);
        sum1 += __shfl_xor_sync(0xffffffffu, sum1, 1);
        sum1 += __shfl_xor_sync(0xffffffffu, sum1, 2);
        l0 = l0 * cor0 + sum0;
        l1 = l1 * cor1 + sum1;
        #pragma unroll
        for (int nt = 0; nt < 8; nt++) {
            o[nt][0] *= cor0; o[nt][1] *= cor0;
            o[nt][2] *= cor1; o[nt][3] *= cor1;
        }

        // write P to warp-private smem region, reload as A-frags
        {
            float* pr0 = sPf + (size_t)(wm + (lane >> 2)) * 132 + 2 * (lane & 3);
            float* pr1 = pr0 + 8 * 132;
            #pragma unroll
            for (int nt = 0; nt < 16; nt++) {
                *(float2*)(pr0 + nt * 8) = make_float2(s[nt][0], s[nt][1]);
                *(float2*)(pr1 + nt * 8) = make_float2(s[nt][2], s[nt][3]);
            }
        }
        __syncwarp();

        // P @ V^T  (k = 128 keys, n = 64 d)
        #pragma unroll
        for (int ks2 = 0; ks2 < 16; ks2++) {
            uint32_t af[4];
            ldsm4(af[0], af[1], af[2], af[3], aP + ks2 * 32);
            uint32_t bf2[8][2];
            #pragma unroll
            for (int p = 0; p < 4; p++) {
                const uint32_t addr =
                    sVu + (uint32_t)((((p << 1) + (lq >> 1)) * 8 + lr) * 132 + ((lq & 1) << 2)) * 4
                        + ks2 * 32;
                ldsm4(bf2[2 * p][0], bf2[2 * p][1], bf2[2 * p + 1][0], bf2[2 * p + 1][1], addr);
            }
            #pragma unroll
            for (int nt = 0; nt < 8; nt++)
                mma_tf32(o[nt], af, bf2[nt]);
        }
        __syncthreads();
    }

    // finalize: divide by l, round, store
    const float inv0 = 1.f / l0, inv1 = 1.f / l1;
    float* ob = out + ((size_t)b * 1024 + q0 + wm + (lane >> 2)) * 1024 + h * 64 + 2 * (lane & 3);
    #pragma unroll
    for (int nt = 0; nt < 8; nt++) {
        *(float2*)(ob + nt * 8) =
            make_float2(tf32r(o[nt][0] * inv0), tf32r(o[nt][1] * inv0));
        *(float2*)(ob + 8 * 1024 + nt * 8) =
            make_float2(tf32r(o[nt][2] * inv1), tf32r(o[nt][3] * inv1));
    }
}

// ---------------------------------------------------------------------------
// LayerNorm over D=1024, tf32-rounded output.
// ---------------------------------------------------------------------------
__global__ __launch_bounds__(256) void ln_kernel(
    const float* __restrict__ in, const float* __restrict__ sc,
    const float* __restrict__ bi, float* __restrict__ out)
{
    const int row = blockIdx.x;
    const int t = threadIdx.x;
    const float4* x4 = (const float4*)(in + (size_t)row * 1024);
    float4 v = x4[t];
    float s  = v.x + v.y + v.z + v.w;
    float ss = v.x * v.x + v.y * v.y + v.z * v.z + v.w * v.w;
    #pragma unroll
    for (int o = 16; o; o >>= 1) {
        s  += __shfl_xor_sync(0xffffffffu, s,  o);
        ss += __shfl_xor_sync(0xffffffffu, ss, o);
    }
    __shared__ float sred[8], ssred[8];
    if ((t & 31) == 0) { sred[t >> 5] = s; ssred[t >> 5] = ss; }
    __syncthreads();
    float tot = 0.f, tots = 0.f;
    #pragma unroll
    for (int w = 0; w < 8; w++) { tot += sred[w]; tots += ssred[w]; }
    const float mean = tot * (1.f / 1024.f);
    const float var  = tots * (1.f / 1024.f) - mean * mean;
    const float inv  = rsqrtf(var + EPSF);
    float4 sv = ((const float4*)sc)[t];
    float4 bv = ((const float4*)bi)[t];
    float4 o4;
    o4.x = tf32r((v.x - mean) * inv * sv.x + bv.x);
    o4.y = tf32r((v.y - mean) * inv * sv.y + bv.y);
    o4.z = tf32r((v.z - mean) * inv * sv.z + bv.z);
    o4.w = tf32r((v.w - mean) * inv * sv.w + bv.w);
    ((float4*)(out + (size_t)row * 1024))[t] = o4;
}

// ---------------------------------------------------------------------------
// QK-norm over DH=64, (H,DH) scale/bias, in-place, tf32-rounded.
// ---------------------------------------------------------------------------
__global__ __launch_bounds__(256) void qknorm_kernel(
    float* __restrict__ q, const float* __restrict__ sc, const float* __restrict__ bi)
{
    const int gw   = (blockIdx.x * 256 + threadIdx.x) >> 5;
    const int lane = threadIdx.x & 31;
    const int h  = gw & 15;
    const int bs = gw >> 4;
    float* p = q + (size_t)bs * 1024 + h * 64;
    float2 v = *(float2*)(p + lane * 2);
    float s  = v.x + v.y;
    float ss = v.x * v.x + v.y * v.y;
    #pragma unroll
    for (int o = 16; o; o >>= 1) {
        s  += __shfl_xor_sync(0xffffffffu, s,  o);
        ss += __shfl_xor_sync(0xffffffffu, ss, o);
    }
    const float mean = s * (1.f / 64.f);
    const float var  = ss * (1.f / 64.f) - mean * mean;
    const float inv  = rsqrtf(var + EPSF);
    const float* scp = sc + h * 64;
    const float* bip = bi + h * 64;
    v.x = tf32r((v.x - mean) * inv * scp[lane * 2 + 0] + bip[lane * 2 + 0]);
    v.y = tf32r((v.y - mean) * inv * scp[lane * 2 + 1] + bip[lane * 2 + 1]);
    *(float2*)(p + lane * 2) = v;
}

// ---------------------------------------------------------------------------
// GeGLU: g1 <- round(g1 * gelu_tanh(g2)).
// ---------------------------------------------------------------------------
__device__ __forceinline__ float gelu_t(float x)
{
    return 0.5f * x * (1.f + tanhf(0.7978845608028654f * (x + 0.044715f * x * x * x)));
}

__global__ __launch_bounds__(256) void geglu_kernel(
    float* __restrict__ g1, const float* __restrict__ g2)
{
    const size_t i = (size_t)blockIdx.x * 256 + threadIdx.x;
    float4 a = ((const float4*)g1)[i];
    float4 c = ((const float4*)g2)[i];
    a.x = tf32r(a.x * gelu_t(c.x));
    a.y = tf32r(a.y * gelu_t(c.y));
    a.z = tf32r(a.z * gelu_t(c.z));
    a.w = tf32r(a.w * gelu_t(c.w));
    ((float4*)g1)[i] = a;
}

// ---------------------------------------------------------------------------
// Launch
// ---------------------------------------------------------------------------
extern "C" void kernel_launch(void* const* d_in, const int* in_sizes, int n_in,
                              void* d_out, int out_size)
{
    (void)in_sizes; (void)n_in; (void)out_size;
    const float* x     = (const float*)d_in[0];
    const float* ln1_s = (const float*)d_in[2];
    const float* ln1_b = (const float*)d_in[3];
    const float* Wq    = (const float*)d_in[4];
    const float* bq    = (const float*)d_in[5];
    const float* Wk    = (const float*)d_in[6];
    const float* bk    = (const float*)d_in[7];
    const float* Wv    = (const float*)d_in[8];
    const float* bv    = (const float*)d_in[9];
    const float* qn_s  = (const float*)d_in[10];
    const float* qn_b  = (const float*)d_in[11];
    const float* kn_s  = (const float*)d_in[12];
    const float* kn_b  = (const float*)d_in[13];
    const float* Wo    = (const float*)d_in[14];
    const float* bo    = (const float*)d_in[15];
    const float* ln2_s = (const float*)d_in[16];
    const float* ln2_b = (const float*)d_in[17];
    const float* W1    = (const float*)d_in[18];
    const float* b1    = (const float*)d_in[19];
    const float* W2    = (const float*)d_in[20];
    const float* b2    = (const float*)d_in[21];
    const float* W3    = (const float*)d_in[22];
    const float* b3    = (const float*)d_in[23];

    float *xn, *q, *k, *v, *res, *big, *wt, *vt;
    cudaGetSymbolAddress((void**)&xn,  g_xn);
    cudaGetSymbolAddress((void**)&q,   g_q);
    cudaGetSymbolAddress((void**)&k,   g_k);
    cudaGetSymbolAddress((void**)&v,   g_v);
    cudaGetSymbolAddress((void**)&res, g_res);
    cudaGetSymbolAddress((void**)&big, g_big);
    cudaGetSymbolAddress((void**)&wt,  g_wt);
    cudaGetSymbolAddress((void**)&vt,  g_vt);

    cudaFuncSetAttribute(flash_kernel, cudaFuncAttributeMaxDynamicSharedMemorySize, FL_SMEM);

    float* out = (float*)d_out;
    const size_t MB1 = 1024 * 1024;
    float* wqt = wt;
    float* wkt = wt + 1 * MB1;
    float* wvt = wt + 2 * MB1;
    float* wot = wt + 3 * MB1;
    float* w1t = wt + 4 * MB1;
    float* w2t = wt + 8 * MB1;
    float* w3t = wt + 12 * MB1;

    // 0. weight transposes + tf32 rounding
    trans_round<<<dim3(32, 32), 256>>>(Wq, wqt, 1024, 1024);
    trans_round<<<dim3(32, 32), 256>>>(Wk, wkt, 1024, 1024);
    trans_round<<<dim3(32, 32), 256>>>(Wv, wvt, 1024, 1024);
    trans_round<<<dim3(32, 32), 256>>>(Wo, wot, 1024, 1024);
    trans_round<<<dim3(128, 32), 256>>>(W1, w1t, 1024, 4096);
    trans_round<<<dim3(128, 32), 256>>>(W2, w2t, 1024, 4096);
    trans_round<<<dim3(32, 128), 256>>>(W3, w3t, 4096, 1024);

    // 1. LN1 (rounded)
    ln_kernel<<<4096, 256>>>(x, ln1_s, ln1_b, xn);

    // 2-4. QKV projections (M=4096, N=1024, K=1024)
    dim3 gqkv(8, 32);
    gemm_mma<0><<<gqkv, 256>>>(xn, wqt, bq, nullptr, q, 1024, 1024, 1024, 1024, 1024);
    gemm_mma<0><<<gqkv, 256>>>(xn, wkt, bk, nullptr, k, 1024, 1024, 1024, 1024, 1024);
    gemm_mma<0><<<gqkv, 256>>>(xn, wvt, bv, nullptr, v, 1024, 1024, 1024, 1024, 1024);

    // 5-6. QK-norm (rounded)
    qknorm_kernel<<<8192, 256>>>(q, qn_s, qn_b);
    qknorm_kernel<<<8192, 256>>>(k, kn_s, kn_b);

    // 6b. v -> vT per batch (rounded)
    trans_round<<<dim3(32, 32, 4), 256>>>(v, vt, 1024, 1024);

    // 7. flash attention -> attn_out into v buffer (q,k still needed as inputs)
    flash_kernel<<<dim3(8, 64), 256, FL_SMEM>>>(q, k, vt, v);

    // 8. O projection + residual
    gemm_mma<1><<<gqkv, 256>>>(v, wot, bo, x, res, 1024, 1024, 1024, 1024, 1024);

    // 9. LN2 (rounded)
    ln_kernel<<<4096, 256>>>(res, ln2_s, ln2_b, xn);

    // 10-11. FFN up (M=4096, N=4096, K=1024)
    dim3 gffn(32, 32);
    float* h1 = big;
    float* h2 = big + (size_t)16777216;
    gemm_mma<0><<<gffn, 256>>>(xn, w1t, b1, nullptr, h1, 4096, 1024, 1024, 1024, 4096);
    gemm_mma<0><<<gffn, 256>>>(xn, w2t, b2, nullptr, h2, 4096, 1024, 1024, 1024, 4096);

    // 12. GeGLU (rounds h1)
    geglu_kernel<<<16384, 256>>>(h1, h2);

    // 13. Down projection + residual -> d_out (M=4096, N=1024, K=4096)
    gemm_mma<1><<<dim3(8, 32), 256>>>(h1, w3t, b3, res, out, 1024, 4096, 4096, 4096, 1024);
}

// round 6
// speedup vs baseline: 5.6782x; 2.0205x over previous
#include <cuda_runtime.h>
#include <cuda_fp16.h>
#include <math.h>
#include <stdint.h>

#define EPSF 1e-6f

// Problem constants: B=4, S=1024, D=1024, H=16, DH=64, F=4096, M=B*S=4096
// Scratch (reinterpreted as half where noted)
__device__ float g_xn [4096 * 1024 / 2];    // xn (half)
__device__ float g_q  [4096 * 1024 / 2];    // q (half)
__device__ float g_k  [4096 * 1024 / 2];    // k (half)
__device__ float g_v  [4096 * 1024 / 2];    // v, then attn_out (half)
__device__ float g_res[4096 * 1024];        // residual after attention (f32)
__device__ float g_big[16 * 1024 * 1024];   // h1/h2 (half, 2x 16M halves)
__device__ float g_wt [8 * 1024 * 1024];    // transposed half weights (16M halves)
__device__ float g_vt [2 * 1024 * 1024];    // vt (half) [b][d][s]

// ---------------------------------------------------------------------------
// Helpers
// ---------------------------------------------------------------------------
__device__ __forceinline__ void cp_async16(uint32_t dst, const void* src)
{
    asm volatile("cp.async.cg.shared.global [%0], [%1], 16;\n" :: "r"(dst), "l"(src));
}
__device__ __forceinline__ void cp_commit() { asm volatile("cp.async.commit_group;\n"); }
__device__ __forceinline__ void cp_wait0()  { asm volatile("cp.async.wait_group 0;\n"); }

__device__ __forceinline__ uint32_t smem_u32(const void* p)
{
    uint32_t a;
    asm("{ .reg .u64 t; cvta.to.shared.u64 t, %1; cvt.u32.u64 %0, t; }" : "=r"(a) : "l"(p));
    return a;
}
__device__ __forceinline__ void ldsm4(uint32_t& r0, uint32_t& r1, uint32_t& r2, uint32_t& r3,
                                      uint32_t a)
{
    asm volatile("ldmatrix.sync.aligned.m8n8.x4.shared.b16 {%0,%1,%2,%3}, [%4];"
                 : "=r"(r0), "=r"(r1), "=r"(r2), "=r"(r3) : "r"(a));
}
__device__ __forceinline__ void mma_h(float c[4], const uint32_t a[4], const uint32_t b[2])
{
    asm volatile(
        "mma.sync.aligned.m16n8k16.row.col.f32.f16.f16.f32 "
        "{%0,%1,%2,%3}, {%4,%5,%6,%7}, {%8,%9}, {%0,%1,%2,%3};\n"
        : "+f"(c[0]), "+f"(c[1]), "+f"(c[2]), "+f"(c[3])
        : "r"(a[0]), "r"(a[1]), "r"(a[2]), "r"(a[3]), "r"(b[0]), "r"(b[1]));
}

// ---------------------------------------------------------------------------
// fp16 tensor-core GEMM: C[M,N] = A[M,K] @ Bt[N,K]^T (+bias)(+Res).
// BM=128 BN=128 BK=32, 256 threads (8 warps, 64x32 warp tiles),
// double-buffered cp.async. Smem row stride 40 halves (80B) -> the 8 ldmatrix
// row addresses cover all 8 distinct 16B segments mod 128B: conflict-free.
// MODE 0: C half = acc + bias
// MODE 1: C float = acc + bias + Res
// ---------------------------------------------------------------------------
template <int MODE>
__global__ __launch_bounds__(256) void gemm_h(
    const __half* __restrict__ A, const __half* __restrict__ B,
    const float* __restrict__ bias, const float* __restrict__ Res,
    void* __restrict__ Cv, int K, int lda, int ldb, int ldc)
{
    __shared__ alignas(16) __half As[2][128 * 40];
    __shared__ alignas(16) __half Bs[2][128 * 40];

    const int t    = threadIdx.x;
    const int lane = t & 31;
    const int warp = t >> 5;
    const size_t m0 = (size_t)blockIdx.y * 128;
    const size_t n0 = (size_t)blockIdx.x * 128;
    const int wm = (warp >> 2) * 64;
    const int wn = (warp & 3) * 32;

    // cp.async maps: 512 chunks (128 rows x 4 x 16B) per matrix, 2/thread
    const uint32_t sA = smem_u32(&As[0][0]);
    const uint32_t sB = smem_u32(&Bs[0][0]);
    constexpr uint32_t STAGE = 128 * 40 * 2;   // bytes

    uint32_t dAo[2], dBo[2];
    const __half* aS[2];
    const __half* bS[2];
    #pragma unroll
    for (int i = 0; i < 2; i++) {
        const int idx = t + 256 * i;
        const int row = idx >> 2, c = idx & 3;
        dAo[i] = (uint32_t)(row * 40 + c * 8) * 2;
        dBo[i] = dAo[i];
        aS[i] = A + (m0 + row) * lda + c * 8;
        bS[i] = B + (n0 + row) * ldb + c * 8;
    }

    const int lq = lane >> 3, lr = lane & 7;
    uint32_t aAddr[4], bAddr[2];
    #pragma unroll
    for (int mt = 0; mt < 4; mt++)
        aAddr[mt] = sA + (uint32_t)((wm + mt * 16 + ((lq & 1) << 3) + lr) * 40 + ((lq >> 1) << 3)) * 2;
    #pragma unroll
    for (int p = 0; p < 2; p++)
        bAddr[p] = sB + (uint32_t)((wn + p * 16 + ((lq >> 1) << 3) + lr) * 40 + ((lq & 1) << 3)) * 2;

    float acc[4][4][4];
    #pragma unroll
    for (int mt = 0; mt < 4; mt++)
        #pragma unroll
        for (int nt = 0; nt < 4; nt++)
            #pragma unroll
            for (int i = 0; i < 4; i++) acc[mt][nt][i] = 0.f;

    auto load_stage = [&](int buf, int k0) {
        #pragma unroll
        for (int i = 0; i < 2; i++) {
            cp_async16(sA - smem_u32(&As[0][0]) + sA + 0, nullptr); // dummy never used
        }
    };
    // (explicit loads below; lambda above unused - removed by optimizer)

    // preload stage 0
    #pragma unroll
    for (int i = 0; i < 2; i++) {
        cp_async16(sA + dAo[i], aS[i]);
        cp_async16(sB + dBo[i], bS[i]);
    }
    cp_commit();

    const int nIter = K >> 5;
    for (int it = 0; it < nIter; ++it) {
        cp_wait0();
        __syncthreads();
        const int buf = it & 1;
        if (it + 1 < nIter) {
            const int k0 = (it + 1) << 5;
            const uint32_t off = (buf ^ 1) * STAGE;
            #pragma unroll
            for (int i = 0; i < 2; i++) {
                cp_async16(sA + off + dAo[i], aS[i] + k0);
                cp_async16(sB + off + dBo[i], bS[i] + k0);
            }
            cp_commit();
        }
        const uint32_t off = buf * STAGE;
        #pragma unroll
        for (int ks = 0; ks < 2; ks++) {
            const uint32_t kB = ks * 32;   // 16 halves
            uint32_t af[4][4];
            #pragma unroll
            for (int mt = 0; mt < 4; mt++)
                ldsm4(af[mt][0], af[mt][1], af[mt][2], af[mt][3], aAddr[mt] + off + kB);
            uint32_t bf[4][2];
            #pragma unroll
            for (int p = 0; p < 2; p++)
                ldsm4(bf[2 * p][0], bf[2 * p][1], bf[2 * p + 1][0], bf[2 * p + 1][1],
                      bAddr[p] + off + kB);
            #pragma unroll
            for (int mt = 0; mt < 4; mt++)
                #pragma unroll
                for (int nt = 0; nt < 4; nt++)
                    mma_h(acc[mt][nt], af[mt], bf[nt]);
        }
        __syncthreads();
    }

    // Epilogue
    #pragma unroll
    for (int mt = 0; mt < 4; mt++) {
        const int r0 = wm + mt * 16 + (lane >> 2);
        #pragma unroll
        for (int nt = 0; nt < 4; nt++) {
            const int c = wn + nt * 8 + (lane & 3) * 2;
            const float b0 = bias[n0 + c], b1 = bias[n0 + c + 1];
            if (MODE == 0) {
                __half* C = (__half*)Cv;
                *(__half2*)(C + (m0 + r0) * ldc + n0 + c) =
                    __floats2half2_rn(acc[mt][nt][0] + b0, acc[mt][nt][1] + b1);
                *(__half2*)(C + (m0 + r0 + 8) * ldc + n0 + c) =
                    __floats2half2_rn(acc[mt][nt][2] + b0, acc[mt][nt][3] + b1);
            } else {
                float* C = (float*)Cv;
                const float* Rr = Res + (m0 + r0) * ldc + n0 + c;
                float2 ra = *(const float2*)Rr;
                float2 rb = *(const float2*)(Rr + 8 * ldc);
                *(float2*)(C + (m0 + r0) * ldc + n0 + c) =
                    make_float2(acc[mt][nt][0] + b0 + ra.x, acc[mt][nt][1] + b1 + ra.y);
                *(float2*)(C + (m0 + r0 + 8) * ldc + n0 + c) =
                    make_float2(acc[mt][nt][2] + b0 + rb.x, acc[mt][nt][3] + b1 + rb.y);
            }
        }
    }
}

// ---------------------------------------------------------------------------
// Transpose f32 -> half: in[R][C] -> out[C][R]
// ---------------------------------------------------------------------------
__global__ __launch_bounds__(256) void trans_f2h(
    const float* __restrict__ in, __half* __restrict__ out, int R, int C)
{
    __shared__ float tile[32][33];
    const int c0 = blockIdx.x * 32, r0 = blockIdx.y * 32;
    const int tx = threadIdx.x & 31, ty = threadIdx.x >> 5;
    #pragma unroll
    for (int i = 0; i < 4; i++)
        tile[ty + 8 * i][tx] = in[(size_t)(r0 + ty + 8 * i) * C + c0 + tx];
    __syncthreads();
    #pragma unroll
    for (int i = 0; i < 4; i++)
        out[(size_t)(c0 + ty + 8 * i) * R + r0 + tx] = __float2half_rn(tile[tx][ty + 8 * i]);
}

// ---------------------------------------------------------------------------
// Transpose half -> half (batched over z): in[R][C] -> out[C][R]
// ---------------------------------------------------------------------------
__global__ __launch_bounds__(256) void trans_h2h(
    const __half* __restrict__ in, __half* __restrict__ out, int R, int C)
{
    __shared__ __half tile[32][34];
    const size_t zoff = (size_t)blockIdx.z * R * C;
    in += zoff; out += zoff;
    const int c0 = blockIdx.x * 32, r0 = blockIdx.y * 32;
    const int tx = threadIdx.x & 31, ty = threadIdx.x >> 5;
    #pragma unroll
    for (int i = 0; i < 4; i++)
        tile[ty + 8 * i][tx] = in[(size_t)(r0 + ty + 8 * i) * C + c0 + tx];
    __syncthreads();
    #pragma unroll
    for (int i = 0; i < 4; i++)
        out[(size_t)(c0 + ty + 8 * i) * R + r0 + tx] = tile[tx][ty + 8 * i];
}

// ---------------------------------------------------------------------------
// Flash attention fp16: per CTA one 128-row Q tile x one (b,h); 8 key tiles
// of 128; f32 online softmax; P bounced via warp-private smem as half.
// smem: K[128][72]h | Vt[64][136]h | P[128][136]h (P doubles as Q staging)
// ---------------------------------------------------------------------------
#define FL_SMEM ((128 * 72 + 64 * 136 + 128 * 136) * 2)

__global__ __launch_bounds__(256) void flash_h(
    const __half* __restrict__ q, const __half* __restrict__ k,
    const __half* __restrict__ vt, __half* __restrict__ out)
{
    extern __shared__ __half smh[];
    const uint32_t sK = smem_u32(smh);
    const uint32_t sV = sK + 128 * 72 * 2;
    const uint32_t sP = sV + 64 * 136 * 2;
    __half* sPh = smh + 128 * 72 + 64 * 136;

    const int t = threadIdx.x;
    const int lane = t & 31, warp = t >> 5;
    const int lq = lane >> 3, lr = lane & 7;
    const int bh = blockIdx.y, b = bh >> 4, h = bh & 15;
    const int q0 = blockIdx.x * 128;
    const int wm = warp * 16;

    const __half* qb = q + ((size_t)b * 1024 + q0) * 1024 + h * 64;
    const __half* kb = k + ((size_t)b << 20) + h * 64;
    const __half* vb = vt + ((size_t)b << 20) + (size_t)h * 64 * 1024;

    // stage Q into P region, stride 72 halves
    {
        #pragma unroll
        for (int i = 0; i < 4; i++) {
            const int idx = t + 256 * i;
            const int row = idx >> 3, c = idx & 7;
            cp_async16(sP + (uint32_t)(row * 72 + c * 8) * 2, qb + (size_t)row * 1024 + c * 8);
        }
    }
    cp_commit(); cp_wait0(); __syncthreads();

    uint32_t qf[4][4];
    {
        const uint32_t a0 = sP + (uint32_t)((wm + ((lq & 1) << 3) + lr) * 72 + ((lq >> 1) << 3)) * 2;
        #pragma unroll
        for (int ks = 0; ks < 4; ks++)
            ldsm4(qf[ks][0], qf[ks][1], qf[ks][2], qf[ks][3], a0 + ks * 32);
    }
    __syncthreads();

    float o[8][4];
    #pragma unroll
    for (int i = 0; i < 8; i++)
        #pragma unroll
        for (int j = 0; j < 4; j++) o[i][j] = 0.f;
    float m0 = -1e30f, m1 = -1e30f, l0 = 0.f, l1 = 0.f;

    const uint32_t aP = sP + (uint32_t)((wm + ((lq & 1) << 3) + lr) * 136 + ((lq >> 1) << 3)) * 2;

    for (int it = 0; it < 8; ++it) {
        const int kt0 = it * 128;
        #pragma unroll
        for (int i = 0; i < 4; i++) {   // K tile: 128 rows x 64 halves
            const int idx = t + 256 * i;
            const int row = idx >> 3, c = idx & 7;
            cp_async16(sK + (uint32_t)(row * 72 + c * 8) * 2,
                       kb + (size_t)(kt0 + row) * 1024 + c * 8);
        }
        #pragma unroll
        for (int i = 0; i < 4; i++) {   // Vt tile: 64 rows x 128 halves
            const int idx = t + 256 * i;
            const int row = idx >> 4, c = idx & 15;
            cp_async16(sV + (uint32_t)(row * 136 + c * 8) * 2,
                       vb + (size_t)row * 1024 + kt0 + c * 8);
        }
        cp_commit(); cp_wait0(); __syncthreads();

        // scores: 16 rows x 128 keys per warp, K=64 over 4 k16 slices
        float s[16][4];
        #pragma unroll
        for (int i = 0; i < 16; i++)
            #pragma unroll
            for (int j = 0; j < 4; j++) s[i][j] = 0.f;
        #pragma unroll
        for (int ks = 0; ks < 4; ks++) {
            uint32_t bf[16][2];
            #pragma unroll
            for (int p = 0; p < 8; p++) {
                const uint32_t addr =
                    sK + (uint32_t)((p * 16 + ((lq >> 1) << 3) + lr) * 72 + ((lq & 1) << 3)) * 2
                       + ks * 32;
                ldsm4(bf[2 * p][0], bf[2 * p][1], bf[2 * p + 1][0], bf[2 * p + 1][1], addr);
            }
            #pragma unroll
            for (int nt = 0; nt < 16; nt++)
                mma_h(s[nt], qf[ks], bf[nt]);
        }

        // online softmax (scale 0.125)
        float c0v = -1e30f, c1v = -1e30f;
        #pragma unroll
        for (int nt = 0; nt < 16; nt++) {
            c0v = fmaxf(c0v, fmaxf(s[nt][0], s[nt][1]));
            c1v = fmaxf(c1v, fmaxf(s[nt][2], s[nt][3]));
        }
        c0v = fmaxf(c0v, __shfl_xor_sync(0xffffffffu, c0v, 1));
        c0v = fmaxf(c0v, __shfl_xor_sync(0xffffffffu, c0v, 2));
        c1v = fmaxf(c1v, __shfl_xor_sync(0xffffffffu, c1v, 1));
        c1v = fmaxf(c1v, __shfl_xor_sync(0xffffffffu, c1v, 2));
        const float m0n = fmaxf(m0, c0v * 0.125f);
        const float m1n = fmaxf(m1, c1v * 0.125f);
        const float cor0 = __expf(m0 - m0n);
        const float cor1 = __expf(m1 - m1n);
        m0 = m0n; m1 = m1n;
        float sum0 = 0.f, sum1 = 0.f;
        // P -> warp-private smem (half), accumulate row sums in f32
        {
            __half* pr0 = sPh + (size_t)(wm + (lane >> 2)) * 136 + 2 * (lane & 3);
            __half* pr1 = pr0 + 8 * 136;
            #pragma unroll
            for (int nt = 0; nt < 16; nt++) {
                float p0 = __expf(fmaf(0.125f, s[nt][0], -m0n));
                float p1 = __expf(fmaf(0.125f, s[nt][1], -m0n));
                float p2 = __expf(fmaf(0.125f, s[nt][2], -m1n));
                float p3 = __expf(fmaf(0.125f, s[nt][3], -m1n));
                sum0 += p0 + p1; sum1 += p2 + p3;
                *(__half2*)(pr0 + nt * 8) = __floats2half2_rn(p0, p1);
                *(__half2*)(pr1 + nt * 8) = __floats2half2_rn(p2, p3);
            }
        }
        sum0 += __shfl_xor_sync(0xffffffffu, sum0, 1);
        sum0 += __shfl_xor_sync(0xffffffffu, sum0, 2);
        sum1 += __shfl_xor_sync(0xffffffffu, sum1, 1);
        sum1 += __shfl_xor_sync(0xffffffffu, sum1, 2);
        l0 = l0 * cor0 + sum0;
        l1 = l1 * cor1 + sum1;
        #pragma unroll
        for (int nt = 0; nt < 8; nt++) {
            o[nt][0] *= cor0; o[nt][1] *= cor0;
            o[nt][2] *= cor1; o[nt][3] *= cor1;
        }
        __syncwarp();

        // P @ Vt: k = 128 keys over 8 k16 slices, n = 64 d
        #pragma unroll
        for (int ks2 = 0; ks2 < 8; ks2++) {
            uint32_t af[4];
            ldsm4(af[0], af[1], af[2], af[3], aP + ks2 * 32);
            uint32_t bf2[8][2];
            #pragma unroll
            for (int p = 0; p < 4; p++) {
                const uint32_t addr =
                    sV + (uint32_t)((p * 16 + ((lq >> 1) << 3) + lr) * 136 + ((lq & 1) << 3)) * 2
                       + ks2 * 32;
                ldsm4(bf2[2 * p][0], bf2[2 * p][1], bf2[2 * p + 1][0], bf2[2 * p + 1][1], addr);
            }
            #pragma unroll
            for (int nt = 0; nt < 8; nt++)
                mma_h(o[nt], af, bf2[nt]);
        }
        __syncthreads();
    }

    const float inv0 = 1.f / l0, inv1 = 1.f / l1;
    __half* ob = out + ((size_t)b * 1024 + q0 + wm + (lane >> 2)) * 1024 + h * 64 + 2 * (lane & 3);
    #pragma unroll
    for (int nt = 0; nt < 8; nt++) {
        *(__half2*)(ob + nt * 8) = __floats2half2_rn(o[nt][0] * inv0, o[nt][1] * inv0);
        *(__half2*)(ob + 8 * 1024 + nt * 8) = __floats2half2_rn(o[nt][2] * inv1, o[nt][3] * inv1);
    }
}

// ---------------------------------------------------------------------------
// LayerNorm over D=1024, f32 in -> half out.
// ---------------------------------------------------------------------------
__global__ __launch_bounds__(256) void ln_kernel(
    const float* __restrict__ in, const float* __restrict__ sc,
    const float* __restrict__ bi, __half* __restrict__ out)
{
    const int row = blockIdx.x;
    const int t = threadIdx.x;
    const float4* x4 = (const float4*)(in + (size_t)row * 1024);
    float4 v = x4[t];
    float s  = v.x + v.y + v.z + v.w;
    float ss = v.x * v.x + v.y * v.y + v.z * v.z + v.w * v.w;
    #pragma unroll
    for (int o = 16; o; o >>= 1) {
        s  += __shfl_xor_sync(0xffffffffu, s,  o);
        ss += __shfl_xor_sync(0xffffffffu, ss, o);
    }
    __shared__ float sred[8], ssred[8];
    if ((t & 31) == 0) { sred[t >> 5] = s; ssred[t >> 5] = ss; }
    __syncthreads();
    float tot = 0.f, tots = 0.f;
    #pragma unroll
    for (int w = 0; w < 8; w++) { tot += sred[w]; tots += ssred[w]; }
    const float mean = tot * (1.f / 1024.f);
    const float var  = tots * (1.f / 1024.f) - mean * mean;
    const float inv  = rsqrtf(var + EPSF);
    float4 sv = ((const float4*)sc)[t];
    float4 bv = ((const float4*)bi)[t];
    __half2* o2 = (__half2*)(out + (size_t)row * 1024);
    o2[t * 2 + 0] = __floats2half2_rn((v.x - mean) * inv * sv.x + bv.x,
                                      (v.y - mean) * inv * sv.y + bv.y);
    o2[t * 2 + 1] = __floats2half2_rn((v.z - mean) * inv * sv.z + bv.z,
                                      (v.w - mean) * inv * sv.w + bv.w);
}

// ---------------------------------------------------------------------------
// QK-norm over DH=64 with (H,DH) f32 scale/bias; half in-place.
// ---------------------------------------------------------------------------
__global__ __launch_bounds__(256) void qknorm_kernel(
    __half* __restrict__ q, const float* __restrict__ sc, const float* __restrict__ bi)
{
    const int gw   = (blockIdx.x * 256 + threadIdx.x) >> 5;
    const int lane = threadIdx.x & 31;
    const int h  = gw & 15;
    const int bs = gw >> 4;
    __half2* p = (__half2*)(q + (size_t)bs * 1024 + h * 64) + lane;
    float2 v = __half22float2(*p);
    float s  = v.x + v.y;
    float ss = v.x * v.x + v.y * v.y;
    #pragma unroll
    for (int o = 16; o; o >>= 1) {
        s  += __shfl_xor_sync(0xffffffffu, s,  o);
        ss += __shfl_xor_sync(0xffffffffu, ss, o);
    }
    const float mean = s * (1.f / 64.f);
    const float var  = ss * (1.f / 64.f) - mean * mean;
    const float inv  = rsqrtf(var + EPSF);
    const float* scp = sc + h * 64 + lane * 2;
    const float* bip = bi + h * 64 + lane * 2;
    *p = __floats2half2_rn((v.x - mean) * inv * scp[0] + bip[0],
                           (v.y - mean) * inv * scp[1] + bip[1]);
}

// ---------------------------------------------------------------------------
// GeGLU: h1 <- h1 * gelu_tanh(h2), half, 4 halves/thread.
// ---------------------------------------------------------------------------
__device__ __forceinline__ float gelu_t(float x)
{
    return 0.5f * x * (1.f + tanhf(0.7978845608028654f * (x + 0.044715f * x * x * x)));
}

__global__ __launch_bounds__(256) void geglu_kernel(
    __half* __restrict__ g1, const __half* __restrict__ g2)
{
    const size_t i = (size_t)blockIdx.x * 256 + threadIdx.x;
    __half2 a0 = ((const __half2*)g1)[i * 2 + 0];
    __half2 a1 = ((const __half2*)g1)[i * 2 + 1];
    __half2 c0 = ((const __half2*)g2)[i * 2 + 0];
    __half2 c1 = ((const __half2*)g2)[i * 2 + 1];
    float2 af0 = __half22float2(a0), af1 = __half22float2(a1);
    float2 cf0 = __half22float2(c0), cf1 = __half22float2(c1);
    ((__half2*)g1)[i * 2 + 0] =
        __floats2half2_rn(af0.x * gelu_t(cf0.x), af0.y * gelu_t(cf0.y));
    ((__half2*)g1)[i * 2 + 1] =
        __floats2half2_rn(af1.x * gelu_t(cf1.x), af1.y * gelu_t(cf1.y));
}

// ---------------------------------------------------------------------------
// Launch
// ---------------------------------------------------------------------------
extern "C" void kernel_launch(void* const* d_in, const int* in_sizes, int n_in,
                              void* d_out, int out_size)
{
    (void)in_sizes; (void)n_in; (void)out_size;
    const float* x     = (const float*)d_in[0];
    const float* ln1_s = (const float*)d_in[2];
    const float* ln1_b = (const float*)d_in[3];
    const float* Wq    = (const float*)d_in[4];
    const float* bq    = (const float*)d_in[5];
    const float* Wk    = (const float*)d_in[6];
    const float* bk    = (const float*)d_in[7];
    const float* Wv    = (const float*)d_in[8];
    const float* bv    = (const float*)d_in[9];
    const float* qn_s  = (const float*)d_in[10];
    const float* qn_b  = (const float*)d_in[11];
    const float* kn_s  = (const float*)d_in[12];
    const float* kn_b  = (const float*)d_in[13];
    const float* Wo    = (const float*)d_in[14];
    const float* bo    = (const float*)d_in[15];
    const float* ln2_s = (const float*)d_in[16];
    const float* ln2_b = (const float*)d_in[17];
    const float* W1    = (const float*)d_in[18];
    const float* b1    = (const float*)d_in[19];
    const float* W2    = (const float*)d_in[20];
    const float* b2    = (const float*)d_in[21];
    const float* W3    = (const float*)d_in[22];
    const float* b3    = (const float*)d_in[23];

    void *p_xn, *p_q, *p_k, *p_v, *p_res, *p_big, *p_wt, *p_vt;
    cudaGetSymbolAddress(&p_xn,  g_xn);
    cudaGetSymbolAddress(&p_q,   g_q);
    cudaGetSymbolAddress(&p_k,   g_k);
    cudaGetSymbolAddress(&p_v,   g_v);
    cudaGetSymbolAddress(&p_res, g_res);
    cudaGetSymbolAddress(&p_big, g_big);
    cudaGetSymbolAddress(&p_wt,  g_wt);
    cudaGetSymbolAddress(&p_vt,  g_vt);

    __half* xn = (__half*)p_xn;
    __half* qh = (__half*)p_q;
    __half* kh = (__half*)p_k;
    __half* vh = (__half*)p_v;
    float*  res = (float*)p_res;
    __half* wt = (__half*)p_wt;
    __half* vt = (__half*)p_vt;
    __half* h1 = (__half*)p_big;
    __half* h2 = h1 + (size_t)16777216;
    float* out = (float*)d_out;

    cudaFuncSetAttribute(flash_h, cudaFuncAttributeMaxDynamicSharedMemorySize, FL_SMEM);

    const size_t MB1 = 1024 * 1024;
    __half* wqt = wt;
    __half* wkt = wt + 1 * MB1;
    __half* wvt = wt + 2 * MB1;
    __half* wot = wt + 3 * MB1;
    __half* w1t = wt + 4 * MB1;
    __half* w2t = wt + 8 * MB1;
    __half* w3t = wt + 12 * MB1;

    // 0. weight transposes -> half
    trans_f2h<<<dim3(32, 32), 256>>>(Wq, wqt, 1024, 1024);
    trans_f2h<<<dim3(32, 32), 256>>>(Wk, wkt, 1024, 1024);
    trans_f2h<<<dim3(32, 32), 256>>>(Wv, wvt, 1024, 1024);
    trans_f2h<<<dim3(32, 32), 256>>>(Wo, wot, 1024, 1024);
    trans_f2h<<<dim3(128, 32), 256>>>(W1, w1t, 1024, 4096);
    trans_f2h<<<dim3(128, 32), 256>>>(W2, w2t, 1024, 4096);
    trans_f2h<<<dim3(32, 128), 256>>>(W3, w3t, 4096, 1024);

    // 1. LN1 -> xn (half)
    ln_kernel<<<4096, 256>>>(x, ln1_s, ln1_b, xn);

    // 2-4. QKV projections (M=4096, N=1024, K=1024), half out
    dim3 gqkv(8, 32);
    gemm_h<0><<<gqkv, 256>>>(xn, wqt, bq, nullptr, qh, 1024, 1024, 1024, 1024);
    gemm_h<0><<<gqkv, 256>>>(xn, wkt, bk, nullptr, kh, 1024, 1024, 1024, 1024);
    gemm_h<0><<<gqkv, 256>>>(xn, wvt, bv, nullptr, vh, 1024, 1024, 1024, 1024);

    // 5-6. QK-norm (half in-place)
    qknorm_kernel<<<8192, 256>>>(qh, qn_s, qn_b);
    qknorm_kernel<<<8192, 256>>>(kh, kn_s, kn_b);

    // 6b. v -> vt per batch (half)
    trans_h2h<<<dim3(32, 32, 4), 256>>>(vh, vt, 1024, 1024);

    // 7. flash attention -> attn_out overwrites vh
    flash_h<<<dim3(8, 64), 256, FL_SMEM>>>(qh, kh, vt, vh);

    // 8. O projection + residual (f32 out)
    gemm_h<1><<<gqkv, 256>>>(vh, wot, bo, x, res, 1024, 1024, 1024, 1024);

    // 9. LN2 -> xn (half)
    ln_kernel<<<4096, 256>>>(res, ln2_s, ln2_b, xn);

    // 10-11. FFN up (M=4096, N=4096, K=1024), half out
    dim3 gffn(32, 32);
    gemm_h<0><<<gffn, 256>>>(xn, w1t, b1, nullptr, h1, 1024, 1024, 1024, 4096);
    gemm_h<0><<<gffn, 256>>>(xn, w2t, b2, nullptr, h2, 1024, 1024, 1024, 4096);

    // 12. GeGLU (half)
    geglu_kernel<<<16384, 256>>>(h1, h2);

    // 13. Down projection + residual -> d_out (M=4096, N=1024, K=4096)
    gemm_h<1><<<dim3(8, 32), 256>>>(h1, w3t, b3, res, out, 4096, 4096, 4096, 1024);
}